// round 6
// baseline (speedup 1.0000x reference)
#include <cuda_runtime.h>
#include <math.h>

// Problem constants (shapes are fixed by the reference)
#define NN 4096
#define DD 256
#define EDD 64
#define HH 8
#define HDIM 32

// ---------------- scratch (device globals; no allocation allowed) ----------
__device__ float g_agg[NN * DD];
__device__ float g_h  [NN * DD];
__device__ float g_t1 [NN * DD];
__device__ float g_h2 [NN * DD];
__device__ float g_x1 [NN * DD];
__device__ float g_qkv[NN * 3 * DD];
__device__ float g_ao [NN * DD];
__device__ float g_o2 [NN * DD];
__device__ float g_x2 [NN * DD];
__device__ float g_f1 [NN * 2 * DD];
__device__ float g_f2 [NN * DD];
__device__ int   g_idx_is64;

// Compile-time scratch-buffer selector (resolved in device code; no host-side
// cudaGetSymbolAddress anywhere).
template <int ID>
__device__ __forceinline__ float* dbuf() {
    if constexpr (ID == 0)  return g_agg;
    else if constexpr (ID == 1)  return g_h;
    else if constexpr (ID == 2)  return g_t1;
    else if constexpr (ID == 3)  return g_h2;
    else if constexpr (ID == 4)  return g_x1;
    else if constexpr (ID == 5)  return g_qkv;
    else if constexpr (ID == 6)  return g_ao;
    else if constexpr (ID == 7)  return g_o2;
    else if constexpr (ID == 8)  return g_x2;
    else if constexpr (ID == 9)  return g_f1;
    else return g_f2;  // 10
}

// ---------------- utilities ----------------
__global__ void zero_agg_kernel(int n) {
    int i = blockIdx.x * blockDim.x + threadIdx.x;
    if (i < n) g_agg[i] = 0.f;
}

// Detect edge_index element width. For int64 (little-endian) with values in
// [0, 4096), every odd 32-bit word is 0. For int32 data, odd words are random
// node indices — the OR over 256 of them is nonzero w.p. 1 - 4096^-256.
__global__ void detect_idx_kernel(const unsigned int* __restrict__ ei32) {
    unsigned int o = 0;
#pragma unroll
    for (int i = 1; i < 512; i += 2) o |= ei32[i];
    g_idx_is64 = (o == 0u) ? 1 : 0;
}

// g_h = (1+eps)*x + g_agg
__global__ void combine_kernel(const float* __restrict__ x,
                               const float* __restrict__ eps, int n) {
    int i = blockIdx.x * blockDim.x + threadIdx.x;
    float c = 1.0f + eps[0];
    if (i < n) g_h[i] = c * x[i] + g_agg[i];
}

// ---------------- GINE edge kernel ----------------
// msg = relu(x[src] + edge_attr @ Wl + bl), g_agg[dst] += msg (scalar atomics)
// 256 threads: each thread owns one output column d; Wl[:,d] lives in registers.
// Edges processed in groups of 4: stage edge_attr -> compute msg -> scatter.
#define EPB 256
__global__ void __launch_bounds__(256, 2) gine_edge_kernel(
    const float* __restrict__ x, const void* __restrict__ ei,
    const float* __restrict__ ea, const float* __restrict__ Wl,
    const float* __restrict__ bl, int E)
{
    const int d = threadIdx.x;
    const int is64 = g_idx_is64;

    float wl[EDD];
#pragma unroll
    for (int k = 0; k < EDD; k++) wl[k] = Wl[k * DD + d];
    const float blv = bl[d];

    __shared__ __align__(16) float ea_s[4 * EDD];
    __shared__ __align__(16) float msg_s[4 * DD];
    __shared__ int ssrc[4];
    __shared__ int sdst[4];

    int e0 = blockIdx.x * EPB;
    int eend = e0 + EPB; if (eend > E) eend = E;

    for (int eg = e0; eg < eend; eg += 4) {
        int ecount = eend - eg; if (ecount > 4) ecount = 4;
        __syncthreads();  // protect ea_s/ssrc/sdst/msg_s from previous group
        if (d < ecount) {
            int sv, dv;
            if (is64) {
                sv = (int)((const long long*)ei)[eg + d];
                dv = (int)((const long long*)ei)[E + eg + d];
            } else {
                sv = ((const int*)ei)[eg + d];
                dv = ((const int*)ei)[E + eg + d];
            }
            // mask is a no-op on valid data (indices in [0, 4096)), but makes
            // OOB scatter/gather structurally impossible
            ssrc[d] = sv & (NN - 1);
            sdst[d] = dv & (NN - 1);
        }
        if (d < ecount * EDD) ea_s[d] = ea[eg * EDD + d];
        __syncthreads();

        float xv[4];
#pragma unroll
        for (int el = 0; el < 4; el++)
            xv[el] = (el < ecount) ? x[ssrc[el] * DD + d] : 0.f;

#pragma unroll
        for (int el = 0; el < 4; el++) {
            if (el < ecount) {
                float acc = blv;
                const float4* e4 = (const float4*)(ea_s + el * EDD);
#pragma unroll
                for (int kk = 0; kk < EDD / 4; kk++) {
                    float4 a = e4[kk];
                    acc = fmaf(a.x, wl[4 * kk + 0], acc);
                    acc = fmaf(a.y, wl[4 * kk + 1], acc);
                    acc = fmaf(a.z, wl[4 * kk + 2], acc);
                    acc = fmaf(a.w, wl[4 * kk + 3], acc);
                }
                float mv = xv[el] + acc;
                msg_s[el * DD + d] = mv > 0.f ? mv : 0.f;
            }
        }
        __syncthreads();

        // scatter: 64 threads per edge, 4 consecutive floats each -> scalar REDG
        int el = d >> 6;
        if (el < ecount) {
            int c = (d & 63) << 2;
            const float* mv = msg_s + el * DD + c;
            float* dst = g_agg + (size_t)sdst[el] * DD + c;
            atomicAdd(dst + 0, mv[0]);
            atomicAdd(dst + 1, mv[1]);
            atomicAdd(dst + 2, mv[2]);
            atomicAdd(dst + 3, mv[3]);
        }
    }
}

// ---------------- generic fused GEMM ----------------
// C[M,Nn] = act(A[M,K] @ B + bias), B normal [K,Nn] or TB: B [Nn,K] (C=A@B^T)
// A and C are scratch buffers selected at compile time; B/bias are weights.
// BM=128, BN=64, BK=16, 256 threads, 8x4 micro-tile, register prefetch.
template <int ACT>
__device__ __forceinline__ float act_fn(float v) {
    if (ACT == 1) return v > 0.f ? v : expm1f(v);                           // ELU
    if (ACT == 2) return 0.5f * v * (1.f + erff(v * 0.7071067811865476f));  // exact GELU
    return v;
}

template <int ACT, bool TB, int AID, int CID>
__global__ void __launch_bounds__(256) gemm_kernel(
    const float* __restrict__ B, const float* __restrict__ bias,
    int M, int Nn, int K)
{
    const float* __restrict__ A = dbuf<AID>();
    float* __restrict__ C = dbuf<CID>();

    __shared__ __align__(16) float As[16][132];
    __shared__ __align__(16) float Bs[16][68];

    const int tid  = threadIdx.x;
    const int row0 = blockIdx.y * 128;
    const int col0 = blockIdx.x * 64;
    const int tyr  = tid >> 4;    // 0..15 (row group of 8)
    const int txc  = tid & 15;    // 0..15 (col group of 4)

    const int ar  = tid >> 2;     // 0..63 (A row within half-tile)
    const int ak4 = tid & 3;      // which float4 along k

    float4 pa0, pa1, pb;
    float acc[8][4];
#pragma unroll
    for (int i = 0; i < 8; i++)
#pragma unroll
        for (int j = 0; j < 4; j++) acc[i][j] = 0.f;

    auto loadT = [&](int kb) {
        const float* Ab = A + (row0) * K + kb * 16;
        pa0 = *(const float4*)(Ab + (ar)      * K + ak4 * 4);
        pa1 = *(const float4*)(Ab + (ar + 64) * K + ak4 * 4);
        if (TB) {
            const float* Bb = B + col0 * K + kb * 16;
            pb = *(const float4*)(Bb + (tid >> 2) * K + (tid & 3) * 4);
        } else {
            const float* Bb = B + (kb * 16) * Nn + col0;
            pb = *(const float4*)(Bb + (tid >> 4) * Nn + (tid & 15) * 4);
        }
    };
    auto storeT = [&]() {
        As[ak4 * 4 + 0][ar]      = pa0.x;
        As[ak4 * 4 + 1][ar]      = pa0.y;
        As[ak4 * 4 + 2][ar]      = pa0.z;
        As[ak4 * 4 + 3][ar]      = pa0.w;
        As[ak4 * 4 + 0][ar + 64] = pa1.x;
        As[ak4 * 4 + 1][ar + 64] = pa1.y;
        As[ak4 * 4 + 2][ar + 64] = pa1.z;
        As[ak4 * 4 + 3][ar + 64] = pa1.w;
        if (TB) {
            int c = tid >> 2, k4 = tid & 3;
            Bs[k4 * 4 + 0][c] = pb.x;
            Bs[k4 * 4 + 1][c] = pb.y;
            Bs[k4 * 4 + 2][c] = pb.z;
            Bs[k4 * 4 + 3][c] = pb.w;
        } else {
            *(float4*)&Bs[tid >> 4][(tid & 15) * 4] = pb;
        }
    };

    const int nk = K >> 4;
    loadT(0);
    storeT();
    __syncthreads();

    for (int kb = 0; kb < nk; kb++) {
        if (kb + 1 < nk) loadT(kb + 1);
#pragma unroll
        for (int kk = 0; kk < 16; kk++) {
            float4 a0 = *(const float4*)&As[kk][tyr * 8];
            float4 a1 = *(const float4*)&As[kk][tyr * 8 + 4];
            float4 b  = *(const float4*)&Bs[kk][txc * 4];
            float av[8] = {a0.x, a0.y, a0.z, a0.w, a1.x, a1.y, a1.z, a1.w};
            float bv[4] = {b.x, b.y, b.z, b.w};
#pragma unroll
            for (int i = 0; i < 8; i++)
#pragma unroll
                for (int j = 0; j < 4; j++)
                    acc[i][j] = fmaf(av[i], bv[j], acc[i][j]);
        }
        __syncthreads();
        if (kb + 1 < nk) {
            storeT();
            __syncthreads();
        }
    }

    const int c = col0 + txc * 4;
    float b0 = bias[c], b1 = bias[c + 1], b2 = bias[c + 2], b3 = bias[c + 3];
#pragma unroll
    for (int i = 0; i < 8; i++) {
        int r = row0 + tyr * 8 + i;
        float4 o;
        o.x = act_fn<ACT>(acc[i][0] + b0);
        o.y = act_fn<ACT>(acc[i][1] + b1);
        o.z = act_fn<ACT>(acc[i][2] + b2);
        o.w = act_fn<ACT>(acc[i][3] + b3);
        *(float4*)&C[r * Nn + c] = o;
    }
}

// ---------------- LayerNorm + residual ----------------
// out = base + (ELU ? elu(ln(f)) : ln(f)),  D = 256, one block per row.
// BASEID/OUTID == -1 selects the external pointer param.
template <int ELU, int BASEID, int FID, int OUTID>
__global__ void __launch_bounds__(256) ln_res_kernel(
    const float* __restrict__ base_ext, float* __restrict__ out_ext,
    const float* __restrict__ gam, const float* __restrict__ bet)
{
    const float* __restrict__ base = (BASEID < 0) ? base_ext : dbuf<(BASEID < 0) ? 0 : BASEID>();
    const float* __restrict__ f = dbuf<FID>();
    float* __restrict__ out = (OUTID < 0) ? out_ext : dbuf<(OUTID < 0) ? 0 : OUTID>();

    const int r = blockIdx.x, t = threadIdx.x;
    float v = f[r * DD + t];
    __shared__ float red[8];
    __shared__ float sh_mu, sh_var;

    float s = v;
#pragma unroll
    for (int o = 16; o; o >>= 1) s += __shfl_xor_sync(0xffffffffu, s, o);
    if ((t & 31) == 0) red[t >> 5] = s;
    __syncthreads();
    if (t == 0) {
        float tot = 0.f;
#pragma unroll
        for (int i = 0; i < 8; i++) tot += red[i];
        sh_mu = tot * (1.f / 256.f);
    }
    __syncthreads();
    const float mu = sh_mu;
    const float dv = v - mu;

    s = dv * dv;
#pragma unroll
    for (int o = 16; o; o >>= 1) s += __shfl_xor_sync(0xffffffffu, s, o);
    if ((t & 31) == 0) red[t >> 5] = s;
    __syncthreads();
    if (t == 0) {
        float tot = 0.f;
#pragma unroll
        for (int i = 0; i < 8; i++) tot += red[i];
        sh_var = tot * (1.f / 256.f);
    }
    __syncthreads();

    float y = dv * rsqrtf(sh_var + 1e-5f) * gam[t] + bet[t];
    if (ELU) y = y > 0.f ? y : expm1f(y);
    out[r * DD + t] = base[r * DD + t] + y;
}

// ---------------- flash attention (fp32, one-pass online softmax) ----------
// grid (N/128, H), 128 threads, thread = one query. K/V tiles of 64 in SMEM
// (reads are warp-uniform -> SMEM broadcast, N=1 cost). qkv=g_qkv, out=g_ao.
__global__ void __launch_bounds__(128) attn_kernel(int N)
{
    const float* __restrict__ qkv = g_qkv;
    float* __restrict__ outp = g_ao;

    __shared__ __align__(16) float Ks[64][36];
    __shared__ __align__(16) float Vs[64][36];
    const int h = blockIdx.y;
    const int t = threadIdx.x;
    const int q = blockIdx.x * 128 + t;

    float qr[HDIM];
    {
        const float4* qp = (const float4*)(qkv + q * (3 * DD) + h * HDIM);
#pragma unroll
        for (int i = 0; i < 8; i++) {
            float4 v = qp[i];
            qr[4 * i] = v.x; qr[4 * i + 1] = v.y; qr[4 * i + 2] = v.z; qr[4 * i + 3] = v.w;
        }
    }
    float oo[HDIM];
#pragma unroll
    for (int i = 0; i < HDIM; i++) oo[i] = 0.f;
    float m = -1e30f, l = 0.f;
    const float sc = 0.17677669529663687f;  // 1/sqrt(32)

    const int nt = N >> 6;
    for (int kb = 0; kb < nt; kb++) {
        __syncthreads();
#pragma unroll
        for (int i = 0; i < 8; i++) {
            int sl  = t + i * 128;           // 0..1023 float4 slots
            int mat = sl >> 9;               // 0 = K, 1 = V
            int rr  = (sl >> 3) & 63;        // key row
            int q4  = sl & 7;
            float4 v = *(const float4*)(qkv + (kb * 64 + rr) * (3 * DD) + DD
                                        + (mat << 8) + h * HDIM + q4 * 4);
            float* dst = (mat ? &Vs[0][0] : &Ks[0][0]) + rr * 36 + q4 * 4;
            *(float4*)dst = v;
        }
        __syncthreads();

#pragma unroll 2
        for (int j = 0; j < 64; j++) {
            const float* kr = &Ks[j][0];
            float s0 = 0.f, s1 = 0.f, s2 = 0.f, s3 = 0.f;
#pragma unroll
            for (int dd = 0; dd < 8; dd++) {
                float4 kv = *(const float4*)(kr + dd * 4);
                s0 = fmaf(qr[4 * dd + 0], kv.x, s0);
                s1 = fmaf(qr[4 * dd + 1], kv.y, s1);
                s2 = fmaf(qr[4 * dd + 2], kv.z, s2);
                s3 = fmaf(qr[4 * dd + 3], kv.w, s3);
            }
            float sv = ((s0 + s1) + (s2 + s3)) * sc;
            float p;
            if (sv <= m) {
                p = __expf(sv - m);
            } else {
                float cor = __expf(m - sv);
                l *= cor;
#pragma unroll
                for (int dd = 0; dd < HDIM; dd++) oo[dd] *= cor;
                m = sv;
                p = 1.f;
            }
            l += p;
            const float* vr = &Vs[j][0];
#pragma unroll
            for (int dd = 0; dd < 8; dd++) {
                float4 vv = *(const float4*)(vr + dd * 4);
                oo[4 * dd + 0] = fmaf(p, vv.x, oo[4 * dd + 0]);
                oo[4 * dd + 1] = fmaf(p, vv.y, oo[4 * dd + 1]);
                oo[4 * dd + 2] = fmaf(p, vv.z, oo[4 * dd + 2]);
                oo[4 * dd + 3] = fmaf(p, vv.w, oo[4 * dd + 3]);
            }
        }
    }

    const float inv = 1.f / l;
    float* op = outp + q * DD + h * HDIM;
#pragma unroll
    for (int i = 0; i < 8; i++) {
        float4 v;
        v.x = oo[4 * i + 0] * inv;
        v.y = oo[4 * i + 1] * inv;
        v.z = oo[4 * i + 2] * inv;
        v.w = oo[4 * i + 3] * inv;
        *(float4*)(op + i * 4) = v;
    }
}

// ---------------- host launch ----------------
extern "C" void kernel_launch(void* const* d_in, const int* in_sizes, int n_in,
                              void* d_out, int out_size) {
    const float* x    = (const float*)d_in[0];
    const void*  ei   = (const void*)d_in[1];
    const float* ea   = (const float*)d_in[2];
    const float* eps  = (const float*)d_in[3];
    const float* Wl   = (const float*)d_in[4];
    const float* bl   = (const float*)d_in[5];
    const float* W1   = (const float*)d_in[6];
    const float* b1   = (const float*)d_in[7];
    const float* W2   = (const float*)d_in[8];
    const float* b2   = (const float*)d_in[9];
    const float* lnlg = (const float*)d_in[10];
    const float* lnlb = (const float*)d_in[11];
    const float* inw  = (const float*)d_in[12];
    const float* inb  = (const float*)d_in[13];
    const float* outw = (const float*)d_in[14];
    const float* outb = (const float*)d_in[15];
    const float* lnag = (const float*)d_in[16];
    const float* lnab = (const float*)d_in[17];
    const float* Wf1  = (const float*)d_in[18];
    const float* bf1  = (const float*)d_in[19];
    const float* Wf2  = (const float*)d_in[20];
    const float* bf2  = (const float*)d_in[21];
    const float* lnfg = (const float*)d_in[22];
    const float* lnfb = (const float*)d_in[23];
    float* out = (float*)d_out;

    const int E = in_sizes[1] / 2;
    const int ND = NN * DD;

    // Buffer ids: 0=agg 1=h 2=t1 3=h2 4=x1 5=qkv 6=ao 7=o2 8=x2 9=f1 10=f2

    // GINEConv: agg = segment_sum(relu(x[src] + ea@Wl + bl), dst)
    detect_idx_kernel<<<1, 1>>>((const unsigned int*)ei);
    zero_agg_kernel<<<(ND + 255) / 256, 256>>>(ND);
    gine_edge_kernel<<<(E + EPB - 1) / EPB, 256>>>(x, ei, ea, Wl, bl, E);
    combine_kernel<<<(ND + 255) / 256, 256>>>(x, eps, ND);

    // local MLP: h2 = elu(h@W1+b1)@W2+b2 ; x1 = x + elu(ln_l(h2))
    gemm_kernel<1, false, 1, 2><<<dim3(DD / 64, NN / 128), 256>>>(W1, b1, NN, DD, DD);
    gemm_kernel<0, false, 2, 3><<<dim3(DD / 64, NN / 128), 256>>>(W2, b2, NN, DD, DD);
    ln_res_kernel<1, -1, 3, 4><<<NN, 256>>>(x, nullptr, lnlg, lnlb);

    // attention: qkv = x1 @ in_w^T + in_b ; o = softmax(QK^T/sqrt(hd)) V ; proj
    gemm_kernel<0, true, 4, 5><<<dim3(3 * DD / 64, NN / 128), 256>>>(inw, inb, NN, 3 * DD, DD);
    attn_kernel<<<dim3(NN / 128, HH), 128>>>(NN);
    gemm_kernel<0, true, 6, 7><<<dim3(DD / 64, NN / 128), 256>>>(outw, outb, NN, DD, DD);
    ln_res_kernel<0, 4, 7, 8><<<NN, 256>>>(nullptr, nullptr, lnag, lnab);

    // FFN: f2 = gelu(x2@Wf1+bf1)@Wf2+bf2 ; out = x2 + ln_f(f2)
    gemm_kernel<2, false, 8, 9><<<dim3(2 * DD / 64, NN / 128), 256>>>(Wf1, bf1, NN, 2 * DD, DD);
    gemm_kernel<0, false, 9, 10><<<dim3(DD / 64, NN / 128), 256>>>(Wf2, bf2, NN, DD, 2 * DD);
    ln_res_kernel<0, 8, 10, -1><<<NN, 256>>>(nullptr, out, lnfg, lnfb);
}

// round 7
// speedup vs baseline: 1.1095x; 1.1095x over previous
#include <cuda_runtime.h>
#include <math.h>

// Problem constants (shapes are fixed by the reference)
#define NN 4096
#define DD 256
#define EDD 64
#define HH 8
#define HDIM 32
#define ASPLIT 4   // attention split-K factor

// ---------------- scratch (device globals; no allocation allowed) ----------
__device__ float g_agg[NN * DD];
__device__ float g_h  [NN * DD];
__device__ float g_t1 [NN * DD];
__device__ float g_h2 [NN * DD];
__device__ float g_x1 [NN * DD];
__device__ float g_qkv[NN * 3 * DD];
__device__ float g_ao [NN * DD];
__device__ float g_o2 [NN * DD];
__device__ float g_x2 [NN * DD];
__device__ float g_f1 [NN * 2 * DD];
__device__ float g_f2 [NN * DD];
__device__ float2 g_ml[ASPLIT * NN * HH];            // (m, l) per split/query/head
__device__ float g_opart[ASPLIT * NN * HH * HDIM];   // unnormalized o per split
__device__ int   g_idx_is64;

// Compile-time scratch-buffer selector (resolved in device code; no host-side
// cudaGetSymbolAddress anywhere).
template <int ID>
__device__ __forceinline__ float* dbuf() {
    if constexpr (ID == 0)  return g_agg;
    else if constexpr (ID == 1)  return g_h;
    else if constexpr (ID == 2)  return g_t1;
    else if constexpr (ID == 3)  return g_h2;
    else if constexpr (ID == 4)  return g_x1;
    else if constexpr (ID == 5)  return g_qkv;
    else if constexpr (ID == 6)  return g_ao;
    else if constexpr (ID == 7)  return g_o2;
    else if constexpr (ID == 8)  return g_x2;
    else if constexpr (ID == 9)  return g_f1;
    else return g_f2;  // 10
}

// ---------------- utilities ----------------
__global__ void zero_agg_kernel(int n) {
    int i = blockIdx.x * blockDim.x + threadIdx.x;
    if (i < n) g_agg[i] = 0.f;
}

// Detect edge_index element width. For int64 (little-endian) with values in
// [0, 4096), every odd 32-bit word is 0. For int32 data, odd words are random
// node indices — the OR over 256 of them is nonzero w.p. 1 - 4096^-256.
__global__ void detect_idx_kernel(const unsigned int* __restrict__ ei32) {
    unsigned int o = 0;
#pragma unroll
    for (int i = 1; i < 512; i += 2) o |= ei32[i];
    g_idx_is64 = (o == 0u) ? 1 : 0;
}

// g_h = (1+eps)*x + g_agg
__global__ void combine_kernel(const float* __restrict__ x,
                               const float* __restrict__ eps, int n) {
    int i = blockIdx.x * blockDim.x + threadIdx.x;
    float c = 1.0f + eps[0];
    if (i < n) g_h[i] = c * x[i] + g_agg[i];
}

// ---------------- GINE edge kernel ----------------
// msg = relu(x[src] + edge_attr @ Wl + bl), g_agg[dst] += msg (scalar atomics)
// 256 threads: each thread owns one output column d; Wl[:,d] lives in registers.
// Edges processed in groups of 4: stage edge_attr -> compute msg -> scatter.
#define EPB 256
__global__ void __launch_bounds__(256, 2) gine_edge_kernel(
    const float* __restrict__ x, const void* __restrict__ ei,
    const float* __restrict__ ea, const float* __restrict__ Wl,
    const float* __restrict__ bl, int E)
{
    const int d = threadIdx.x;
    const int is64 = g_idx_is64;

    float wl[EDD];
#pragma unroll
    for (int k = 0; k < EDD; k++) wl[k] = Wl[k * DD + d];
    const float blv = bl[d];

    __shared__ __align__(16) float ea_s[4 * EDD];
    __shared__ __align__(16) float msg_s[4 * DD];
    __shared__ int ssrc[4];
    __shared__ int sdst[4];

    int e0 = blockIdx.x * EPB;
    int eend = e0 + EPB; if (eend > E) eend = E;

    for (int eg = e0; eg < eend; eg += 4) {
        int ecount = eend - eg; if (ecount > 4) ecount = 4;
        __syncthreads();  // protect ea_s/ssrc/sdst/msg_s from previous group
        if (d < ecount) {
            int sv, dv;
            if (is64) {
                sv = (int)((const long long*)ei)[eg + d];
                dv = (int)((const long long*)ei)[E + eg + d];
            } else {
                sv = ((const int*)ei)[eg + d];
                dv = ((const int*)ei)[E + eg + d];
            }
            // mask is a no-op on valid data (indices in [0, 4096)), but makes
            // OOB scatter/gather structurally impossible
            ssrc[d] = sv & (NN - 1);
            sdst[d] = dv & (NN - 1);
        }
        if (d < ecount * EDD) ea_s[d] = ea[eg * EDD + d];
        __syncthreads();

        float xv[4];
#pragma unroll
        for (int el = 0; el < 4; el++)
            xv[el] = (el < ecount) ? x[ssrc[el] * DD + d] : 0.f;

#pragma unroll
        for (int el = 0; el < 4; el++) {
            if (el < ecount) {
                float acc = blv;
                const float4* e4 = (const float4*)(ea_s + el * EDD);
#pragma unroll
                for (int kk = 0; kk < EDD / 4; kk++) {
                    float4 a = e4[kk];
                    acc = fmaf(a.x, wl[4 * kk + 0], acc);
                    acc = fmaf(a.y, wl[4 * kk + 1], acc);
                    acc = fmaf(a.z, wl[4 * kk + 2], acc);
                    acc = fmaf(a.w, wl[4 * kk + 3], acc);
                }
                float mv = xv[el] + acc;
                msg_s[el * DD + d] = mv > 0.f ? mv : 0.f;
            }
        }
        __syncthreads();

        // scatter: 64 threads per edge, 4 consecutive floats each -> scalar REDG
        int el = d >> 6;
        if (el < ecount) {
            int c = (d & 63) << 2;
            const float* mv = msg_s + el * DD + c;
            float* dst = g_agg + (size_t)sdst[el] * DD + c;
            atomicAdd(dst + 0, mv[0]);
            atomicAdd(dst + 1, mv[1]);
            atomicAdd(dst + 2, mv[2]);
            atomicAdd(dst + 3, mv[3]);
        }
    }
}

// ---------------- generic fused GEMM ----------------
// C[M,Nn] = act(A[M,K] @ B + bias), B normal [K,Nn] or TB: B [Nn,K] (C=A@B^T)
// A and C are scratch buffers selected at compile time; B/bias are weights.
// BM=128, BN=64, BK=16, 256 threads, 8x4 micro-tile, register prefetch.
template <int ACT>
__device__ __forceinline__ float act_fn(float v) {
    if (ACT == 1) return v > 0.f ? v : expm1f(v);                           // ELU
    if (ACT == 2) return 0.5f * v * (1.f + erff(v * 0.7071067811865476f));  // exact GELU
    return v;
}

template <int ACT, bool TB, int AID, int CID>
__global__ void __launch_bounds__(256) gemm_kernel(
    const float* __restrict__ B, const float* __restrict__ bias,
    int M, int Nn, int K)
{
    const float* __restrict__ A = dbuf<AID>();
    float* __restrict__ C = dbuf<CID>();

    __shared__ __align__(16) float As[16][132];
    __shared__ __align__(16) float Bs[16][68];

    const int tid  = threadIdx.x;
    const int row0 = blockIdx.y * 128;
    const int col0 = blockIdx.x * 64;
    const int tyr  = tid >> 4;    // 0..15 (row group of 8)
    const int txc  = tid & 15;    // 0..15 (col group of 4)

    const int ar  = tid >> 2;     // 0..63 (A row within half-tile)
    const int ak4 = tid & 3;      // which float4 along k

    float4 pa0, pa1, pb;
    float acc[8][4];
#pragma unroll
    for (int i = 0; i < 8; i++)
#pragma unroll
        for (int j = 0; j < 4; j++) acc[i][j] = 0.f;

    auto loadT = [&](int kb) {
        const float* Ab = A + (row0) * K + kb * 16;
        pa0 = *(const float4*)(Ab + (ar)      * K + ak4 * 4);
        pa1 = *(const float4*)(Ab + (ar + 64) * K + ak4 * 4);
        if (TB) {
            const float* Bb = B + col0 * K + kb * 16;
            pb = *(const float4*)(Bb + (tid >> 2) * K + (tid & 3) * 4);
        } else {
            const float* Bb = B + (kb * 16) * Nn + col0;
            pb = *(const float4*)(Bb + (tid >> 4) * Nn + (tid & 15) * 4);
        }
    };
    auto storeT = [&]() {
        As[ak4 * 4 + 0][ar]      = pa0.x;
        As[ak4 * 4 + 1][ar]      = pa0.y;
        As[ak4 * 4 + 2][ar]      = pa0.z;
        As[ak4 * 4 + 3][ar]      = pa0.w;
        As[ak4 * 4 + 0][ar + 64] = pa1.x;
        As[ak4 * 4 + 1][ar + 64] = pa1.y;
        As[ak4 * 4 + 2][ar + 64] = pa1.z;
        As[ak4 * 4 + 3][ar + 64] = pa1.w;
        if (TB) {
            int c = tid >> 2, k4 = tid & 3;
            Bs[k4 * 4 + 0][c] = pb.x;
            Bs[k4 * 4 + 1][c] = pb.y;
            Bs[k4 * 4 + 2][c] = pb.z;
            Bs[k4 * 4 + 3][c] = pb.w;
        } else {
            *(float4*)&Bs[tid >> 4][(tid & 15) * 4] = pb;
        }
    };

    const int nk = K >> 4;
    loadT(0);
    storeT();
    __syncthreads();

    for (int kb = 0; kb < nk; kb++) {
        if (kb + 1 < nk) loadT(kb + 1);
#pragma unroll
        for (int kk = 0; kk < 16; kk++) {
            float4 a0 = *(const float4*)&As[kk][tyr * 8];
            float4 a1 = *(const float4*)&As[kk][tyr * 8 + 4];
            float4 b  = *(const float4*)&Bs[kk][txc * 4];
            float av[8] = {a0.x, a0.y, a0.z, a0.w, a1.x, a1.y, a1.z, a1.w};
            float bv[4] = {b.x, b.y, b.z, b.w};
#pragma unroll
            for (int i = 0; i < 8; i++)
#pragma unroll
                for (int j = 0; j < 4; j++)
                    acc[i][j] = fmaf(av[i], bv[j], acc[i][j]);
        }
        __syncthreads();
        if (kb + 1 < nk) {
            storeT();
            __syncthreads();
        }
    }

    const int c = col0 + txc * 4;
    float b0 = bias[c], b1 = bias[c + 1], b2 = bias[c + 2], b3 = bias[c + 3];
#pragma unroll
    for (int i = 0; i < 8; i++) {
        int r = row0 + tyr * 8 + i;
        float4 o;
        o.x = act_fn<ACT>(acc[i][0] + b0);
        o.y = act_fn<ACT>(acc[i][1] + b1);
        o.z = act_fn<ACT>(acc[i][2] + b2);
        o.w = act_fn<ACT>(acc[i][3] + b3);
        *(float4*)&C[r * Nn + c] = o;
    }
}

// ---------------- LayerNorm + residual ----------------
// out = base + (ELU ? elu(ln(f)) : ln(f)),  D = 256, one block per row.
// BASEID/OUTID == -1 selects the external pointer param.
template <int ELU, int BASEID, int FID, int OUTID>
__global__ void __launch_bounds__(256) ln_res_kernel(
    const float* __restrict__ base_ext, float* __restrict__ out_ext,
    const float* __restrict__ gam, const float* __restrict__ bet)
{
    const float* __restrict__ base = (BASEID < 0) ? base_ext : dbuf<(BASEID < 0) ? 0 : BASEID>();
    const float* __restrict__ f = dbuf<FID>();
    float* __restrict__ out = (OUTID < 0) ? out_ext : dbuf<(OUTID < 0) ? 0 : OUTID>();

    const int r = blockIdx.x, t = threadIdx.x;
    float v = f[r * DD + t];
    __shared__ float red[8];
    __shared__ float sh_mu, sh_var;

    float s = v;
#pragma unroll
    for (int o = 16; o; o >>= 1) s += __shfl_xor_sync(0xffffffffu, s, o);
    if ((t & 31) == 0) red[t >> 5] = s;
    __syncthreads();
    if (t == 0) {
        float tot = 0.f;
#pragma unroll
        for (int i = 0; i < 8; i++) tot += red[i];
        sh_mu = tot * (1.f / 256.f);
    }
    __syncthreads();
    const float mu = sh_mu;
    const float dv = v - mu;

    s = dv * dv;
#pragma unroll
    for (int o = 16; o; o >>= 1) s += __shfl_xor_sync(0xffffffffu, s, o);
    if ((t & 31) == 0) red[t >> 5] = s;
    __syncthreads();
    if (t == 0) {
        float tot = 0.f;
#pragma unroll
        for (int i = 0; i < 8; i++) tot += red[i];
        sh_var = tot * (1.f / 256.f);
    }
    __syncthreads();

    float y = dv * rsqrtf(sh_var + 1e-5f) * gam[t] + bet[t];
    if (ELU) y = y > 0.f ? y : expm1f(y);
    out[r * DD + t] = base[r * DD + t] + y;
}

// ---------------- flash attention, split-K partials --------------------
// grid (N/128, H, ASPLIT), 128 threads, thread = one query. Each block scans
// keys [s*N/ASPLIT, (s+1)*N/ASPLIT) and emits unnormalized (m, l, o[32]).
// K/V tiles of 64 keys staged in SMEM (reads warp-uniform -> broadcast).
__global__ void __launch_bounds__(128) attn_part_kernel(int N)
{
    const float* __restrict__ qkv = g_qkv;

    __shared__ __align__(16) float Ks[64][36];
    __shared__ __align__(16) float Vs[64][36];
    const int h = blockIdx.y;
    const int s = blockIdx.z;
    const int t = threadIdx.x;
    const int q = blockIdx.x * 128 + t;

    float qr[HDIM];
    {
        const float4* qp = (const float4*)(qkv + q * (3 * DD) + h * HDIM);
#pragma unroll
        for (int i = 0; i < 8; i++) {
            float4 v = qp[i];
            qr[4 * i] = v.x; qr[4 * i + 1] = v.y; qr[4 * i + 2] = v.z; qr[4 * i + 3] = v.w;
        }
    }
    float oo[HDIM];
#pragma unroll
    for (int i = 0; i < HDIM; i++) oo[i] = 0.f;
    float m = -1e30f, l = 0.f;
    const float sc = 0.17677669529663687f;  // 1/sqrt(32)

    const int nt = N / (64 * ASPLIT);       // key tiles per split
    const int kb0 = s * nt;
    for (int kb = kb0; kb < kb0 + nt; kb++) {
        __syncthreads();
#pragma unroll
        for (int i = 0; i < 8; i++) {
            int sl  = t + i * 128;           // 0..1023 float4 slots
            int mat = sl >> 9;               // 0 = K, 1 = V
            int rr  = (sl >> 3) & 63;        // key row
            int q4  = sl & 7;
            float4 v = *(const float4*)(qkv + (kb * 64 + rr) * (3 * DD) + DD
                                        + (mat << 8) + h * HDIM + q4 * 4);
            float* dst = (mat ? &Vs[0][0] : &Ks[0][0]) + rr * 36 + q4 * 4;
            *(float4*)dst = v;
        }
        __syncthreads();

#pragma unroll 2
        for (int j = 0; j < 64; j++) {
            const float* kr = &Ks[j][0];
            float s0 = 0.f, s1 = 0.f, s2 = 0.f, s3 = 0.f;
#pragma unroll
            for (int dd = 0; dd < 8; dd++) {
                float4 kv = *(const float4*)(kr + dd * 4);
                s0 = fmaf(qr[4 * dd + 0], kv.x, s0);
                s1 = fmaf(qr[4 * dd + 1], kv.y, s1);
                s2 = fmaf(qr[4 * dd + 2], kv.z, s2);
                s3 = fmaf(qr[4 * dd + 3], kv.w, s3);
            }
            float sv = ((s0 + s1) + (s2 + s3)) * sc;
            float p;
            if (sv <= m) {
                p = __expf(sv - m);
            } else {
                float cor = __expf(m - sv);
                l *= cor;
#pragma unroll
                for (int dd = 0; dd < HDIM; dd++) oo[dd] *= cor;
                m = sv;
                p = 1.f;
            }
            l += p;
            const float* vr = &Vs[j][0];
#pragma unroll
            for (int dd = 0; dd < 8; dd++) {
                float4 vv = *(const float4*)(vr + dd * 4);
                oo[4 * dd + 0] = fmaf(p, vv.x, oo[4 * dd + 0]);
                oo[4 * dd + 1] = fmaf(p, vv.y, oo[4 * dd + 1]);
                oo[4 * dd + 2] = fmaf(p, vv.z, oo[4 * dd + 2]);
                oo[4 * dd + 3] = fmaf(p, vv.w, oo[4 * dd + 3]);
            }
        }
    }

    const int qh = q * HH + h;
    g_ml[s * (NN * HH) + qh] = make_float2(m, l);
    float* op = g_opart + (size_t)(s * (NN * HH) + qh) * HDIM;
#pragma unroll
    for (int i = 0; i < 8; i++) {
        float4 v;
        v.x = oo[4 * i + 0];
        v.y = oo[4 * i + 1];
        v.z = oo[4 * i + 2];
        v.w = oo[4 * i + 3];
        *(float4*)(op + i * 4) = v;
    }
}

// Merge ASPLIT partials: standard log-sum-exp combine. One thread per output
// element (q, h, dd); g_ao layout [q][h*32+dd] == flat idx.
__global__ void __launch_bounds__(256) attn_reduce_kernel()
{
    const int idx = blockIdx.x * blockDim.x + threadIdx.x;  // N*H*32
    const int dd = idx & (HDIM - 1);
    const int qh = idx >> 5;  // q*H + h

    float2 ml[ASPLIT];
    float M = -1e30f;
#pragma unroll
    for (int s = 0; s < ASPLIT; s++) {
        ml[s] = g_ml[s * (NN * HH) + qh];
        M = fmaxf(M, ml[s].x);
    }
    float L = 0.f, o = 0.f;
#pragma unroll
    for (int s = 0; s < ASPLIT; s++) {
        float w = __expf(ml[s].x - M);
        L = fmaf(ml[s].y, w, L);
        o = fmaf(g_opart[(size_t)(s * (NN * HH) + qh) * HDIM + dd], w, o);
    }
    g_ao[idx] = o / L;
}

// ---------------- host launch ----------------
extern "C" void kernel_launch(void* const* d_in, const int* in_sizes, int n_in,
                              void* d_out, int out_size) {
    const float* x    = (const float*)d_in[0];
    const void*  ei   = (const void*)d_in[1];
    const float* ea   = (const float*)d_in[2];
    const float* eps  = (const float*)d_in[3];
    const float* Wl   = (const float*)d_in[4];
    const float* bl   = (const float*)d_in[5];
    const float* W1   = (const float*)d_in[6];
    const float* b1   = (const float*)d_in[7];
    const float* W2   = (const float*)d_in[8];
    const float* b2   = (const float*)d_in[9];
    const float* lnlg = (const float*)d_in[10];
    const float* lnlb = (const float*)d_in[11];
    const float* inw  = (const float*)d_in[12];
    const float* inb  = (const float*)d_in[13];
    const float* outw = (const float*)d_in[14];
    const float* outb = (const float*)d_in[15];
    const float* lnag = (const float*)d_in[16];
    const float* lnab = (const float*)d_in[17];
    const float* Wf1  = (const float*)d_in[18];
    const float* bf1  = (const float*)d_in[19];
    const float* Wf2  = (const float*)d_in[20];
    const float* bf2  = (const float*)d_in[21];
    const float* lnfg = (const float*)d_in[22];
    const float* lnfb = (const float*)d_in[23];
    float* out = (float*)d_out;

    const int E = in_sizes[1] / 2;
    const int ND = NN * DD;

    // Buffer ids: 0=agg 1=h 2=t1 3=h2 4=x1 5=qkv 6=ao 7=o2 8=x2 9=f1 10=f2

    // GINEConv: agg = segment_sum(relu(x[src] + ea@Wl + bl), dst)
    detect_idx_kernel<<<1, 1>>>((const unsigned int*)ei);
    zero_agg_kernel<<<(ND + 255) / 256, 256>>>(ND);
    gine_edge_kernel<<<(E + EPB - 1) / EPB, 256>>>(x, ei, ea, Wl, bl, E);
    combine_kernel<<<(ND + 255) / 256, 256>>>(x, eps, ND);

    // local MLP: h2 = elu(h@W1+b1)@W2+b2 ; x1 = x + elu(ln_l(h2))
    gemm_kernel<1, false, 1, 2><<<dim3(DD / 64, NN / 128), 256>>>(W1, b1, NN, DD, DD);
    gemm_kernel<0, false, 2, 3><<<dim3(DD / 64, NN / 128), 256>>>(W2, b2, NN, DD, DD);
    ln_res_kernel<1, -1, 3, 4><<<NN, 256>>>(x, nullptr, lnlg, lnlb);

    // attention: qkv = x1 @ in_w^T + in_b ; o = softmax(QK^T/sqrt(hd)) V ; proj
    gemm_kernel<0, true, 4, 5><<<dim3(3 * DD / 64, NN / 128), 256>>>(inw, inb, NN, 3 * DD, DD);
    attn_part_kernel<<<dim3(NN / 128, HH, ASPLIT), 128>>>(NN);
    attn_reduce_kernel<<<(NN * HH * HDIM) / 256, 256>>>();
    gemm_kernel<0, true, 6, 7><<<dim3(DD / 64, NN / 128), 256>>>(outw, outb, NN, DD, DD);
    ln_res_kernel<0, 4, 7, 8><<<NN, 256>>>(nullptr, nullptr, lnag, lnab);

    // FFN: f2 = gelu(x2@Wf1+bf1)@Wf2+bf2 ; out = x2 + ln_f(f2)
    gemm_kernel<2, false, 8, 9><<<dim3(2 * DD / 64, NN / 128), 256>>>(Wf1, bf1, NN, 2 * DD, DD);
    gemm_kernel<0, false, 9, 10><<<dim3(DD / 64, NN / 128), 256>>>(Wf2, bf2, NN, DD, 2 * DD);
    ln_res_kernel<0, 8, 10, -1><<<NN, 256>>>(nullptr, out, lnfg, lnfb);
}

// round 8
// speedup vs baseline: 1.1612x; 1.0466x over previous
#include <cuda_runtime.h>
#include <math.h>

// Problem constants (shapes are fixed by the reference)
#define NN 4096
#define DD 256
#define EDD 64
#define HH 8
#define HDIM 32
#define ASPLIT 4   // attention split-K factor

typedef unsigned long long u64;

// ---------------- packed fp32x2 helpers (sm_103a dual-FP32 path) ----------
__device__ __forceinline__ u64 ffma2(u64 a, u64 b, u64 c) {
    u64 d;
    asm("fma.rn.f32x2 %0, %1, %2, %3;" : "=l"(d) : "l"(a), "l"(b), "l"(c));
    return d;
}
__device__ __forceinline__ u64 fmul2(u64 a, u64 b) {
    u64 d;
    asm("mul.rn.f32x2 %0, %1, %2;" : "=l"(d) : "l"(a), "l"(b));
    return d;
}
__device__ __forceinline__ u64 pack2(float lo, float hi) {
    u64 d;
    asm("mov.b64 %0, {%1, %2};" : "=l"(d) : "f"(lo), "f"(hi));
    return d;
}
__device__ __forceinline__ float2 unpack2(u64 v) {
    float2 r;
    asm("mov.b64 {%0, %1}, %2;" : "=f"(r.x), "=f"(r.y) : "l"(v));
    return r;
}

// ---------------- scratch (device globals; no allocation allowed) ----------
__device__ float g_agg[NN * DD];
__device__ float g_h  [NN * DD];
__device__ float g_t1 [NN * DD];
__device__ float g_h2 [NN * DD];
__device__ float g_x1 [NN * DD];
__device__ float g_qkv[NN * 3 * DD];
__device__ float g_ao [NN * DD];
__device__ float g_o2 [NN * DD];
__device__ float g_x2 [NN * DD];
__device__ float g_f1 [NN * 2 * DD];
__device__ float g_f2 [NN * DD];
__device__ float2 g_ml[ASPLIT * NN * HH];            // (m, l) per split/query/head
__device__ float g_opart[ASPLIT * NN * HH * HDIM];   // unnormalized o per split
__device__ int   g_idx_is64;

// Compile-time scratch-buffer selector (resolved in device code).
template <int ID>
__device__ __forceinline__ float* dbuf() {
    if constexpr (ID == 0)  return g_agg;
    else if constexpr (ID == 1)  return g_h;
    else if constexpr (ID == 2)  return g_t1;
    else if constexpr (ID == 3)  return g_h2;
    else if constexpr (ID == 4)  return g_x1;
    else if constexpr (ID == 5)  return g_qkv;
    else if constexpr (ID == 6)  return g_ao;
    else if constexpr (ID == 7)  return g_o2;
    else if constexpr (ID == 8)  return g_x2;
    else if constexpr (ID == 9)  return g_f1;
    else return g_f2;  // 10
}

// ---------------- utilities ----------------
__global__ void zero_agg_kernel(int n) {
    int i = blockIdx.x * blockDim.x + threadIdx.x;
    if (i < n) g_agg[i] = 0.f;
}

// Detect edge_index element width (int64 vs silently-downcast int32).
__global__ void detect_idx_kernel(const unsigned int* __restrict__ ei32) {
    unsigned int o = 0;
#pragma unroll
    for (int i = 1; i < 512; i += 2) o |= ei32[i];
    g_idx_is64 = (o == 0u) ? 1 : 0;
}

// g_h = (1+eps)*x + g_agg
__global__ void combine_kernel(const float* __restrict__ x,
                               const float* __restrict__ eps, int n) {
    int i = blockIdx.x * blockDim.x + threadIdx.x;
    float c = 1.0f + eps[0];
    if (i < n) g_h[i] = c * x[i] + g_agg[i];
}

// ---------------- GINE edge kernel ----------------
// msg = relu(x[src] + edge_attr @ Wl + bl), g_agg[dst] += msg (scalar atomics)
// 256 threads: thread owns one output column d; Wl[:,d] packed f32x2 in regs.
#define EPB 256
__global__ void __launch_bounds__(256, 2) gine_edge_kernel(
    const float* __restrict__ x, const void* __restrict__ ei,
    const float* __restrict__ ea, const float* __restrict__ Wl,
    const float* __restrict__ bl, int E)
{
    const int d = threadIdx.x;
    const int is64 = g_idx_is64;

    u64 wl2[EDD / 2];
#pragma unroll
    for (int k = 0; k < EDD / 2; k++)
        wl2[k] = pack2(Wl[(2 * k) * DD + d], Wl[(2 * k + 1) * DD + d]);
    const float blv = bl[d];

    __shared__ __align__(16) float ea_s[4 * EDD];
    __shared__ __align__(16) float msg_s[4 * DD];
    __shared__ int ssrc[4];
    __shared__ int sdst[4];

    int e0 = blockIdx.x * EPB;
    int eend = e0 + EPB; if (eend > E) eend = E;

    for (int eg = e0; eg < eend; eg += 4) {
        int ecount = eend - eg; if (ecount > 4) ecount = 4;
        __syncthreads();  // protect ea_s/ssrc/sdst/msg_s from previous group
        if (d < ecount) {
            int sv, dv;
            if (is64) {
                sv = (int)((const long long*)ei)[eg + d];
                dv = (int)((const long long*)ei)[E + eg + d];
            } else {
                sv = ((const int*)ei)[eg + d];
                dv = ((const int*)ei)[E + eg + d];
            }
            ssrc[d] = sv & (NN - 1);
            sdst[d] = dv & (NN - 1);
        }
        if (d < ecount * EDD) ea_s[d] = ea[eg * EDD + d];
        __syncthreads();

        float xv[4];
#pragma unroll
        for (int el = 0; el < 4; el++)
            xv[el] = (el < ecount) ? x[ssrc[el] * DD + d] : 0.f;

#pragma unroll
        for (int el = 0; el < 4; el++) {
            if (el < ecount) {
                u64 acc2a = 0ull, acc2b = 0ull;  // two chains for ILP
                const float4* e4 = (const float4*)(ea_s + el * EDD);
#pragma unroll
                for (int kk = 0; kk < EDD / 4; kk++) {
                    float4 a = e4[kk];
                    acc2a = ffma2(pack2(a.x, a.y), wl2[2 * kk + 0], acc2a);
                    acc2b = ffma2(pack2(a.z, a.w), wl2[2 * kk + 1], acc2b);
                }
                float2 fa = unpack2(acc2a), fb = unpack2(acc2b);
                float mv = xv[el] + blv + ((fa.x + fa.y) + (fb.x + fb.y));
                msg_s[el * DD + d] = mv > 0.f ? mv : 0.f;
            }
        }
        __syncthreads();

        // scatter: 64 threads per edge, 4 consecutive floats each -> scalar REDG
        int el = d >> 6;
        if (el < ecount) {
            int c = (d & 63) << 2;
            const float* mv = msg_s + el * DD + c;
            float* dst = g_agg + (size_t)sdst[el] * DD + c;
            atomicAdd(dst + 0, mv[0]);
            atomicAdd(dst + 1, mv[1]);
            atomicAdd(dst + 2, mv[2]);
            atomicAdd(dst + 3, mv[3]);
        }
    }
}

// ---------------- generic fused GEMM (f32x2 micro-kernel) ----------------
// C[M,Nn] = act(A[M,K] @ B + bias), B normal [K,Nn] or TB: B [Nn,K] (C=A@B^T)
// BM=128, BN=64, BK=16, 256 threads, 8x4 micro-tile packed in i-pairs.
template <int ACT>
__device__ __forceinline__ float act_fn(float v) {
    if (ACT == 1) return v > 0.f ? v : expm1f(v);                           // ELU
    if (ACT == 2) return 0.5f * v * (1.f + erff(v * 0.7071067811865476f));  // exact GELU
    return v;
}

template <int ACT, bool TB, int AID, int CID>
__global__ void __launch_bounds__(256) gemm_kernel(
    const float* __restrict__ B, const float* __restrict__ bias,
    int M, int Nn, int K)
{
    const float* __restrict__ A = dbuf<AID>();
    float* __restrict__ C = dbuf<CID>();

    __shared__ __align__(16) float As[16][132];
    __shared__ __align__(16) float Bs[16][68];

    const int tid  = threadIdx.x;
    const int row0 = blockIdx.y * 128;
    const int col0 = blockIdx.x * 64;
    const int tyr  = tid >> 4;    // 0..15 (row group of 8)
    const int txc  = tid & 15;    // 0..15 (col group of 4)

    const int ar  = tid >> 2;     // 0..63 (A row within half-tile)
    const int ak4 = tid & 3;      // which float4 along k

    float4 pa0, pa1, pb;
    // acc2[ip][j]: rows (tyr*8 + 2ip, +2ip+1), col txc*4 + j
    u64 acc2[4][4];
#pragma unroll
    for (int i = 0; i < 4; i++)
#pragma unroll
        for (int j = 0; j < 4; j++) acc2[i][j] = 0ull;

    auto loadT = [&](int kb) {
        const float* Ab = A + (row0) * K + kb * 16;
        pa0 = *(const float4*)(Ab + (ar)      * K + ak4 * 4);
        pa1 = *(const float4*)(Ab + (ar + 64) * K + ak4 * 4);
        if (TB) {
            const float* Bb = B + col0 * K + kb * 16;
            pb = *(const float4*)(Bb + (tid >> 2) * K + (tid & 3) * 4);
        } else {
            const float* Bb = B + (kb * 16) * Nn + col0;
            pb = *(const float4*)(Bb + (tid >> 4) * Nn + (tid & 15) * 4);
        }
    };
    auto storeT = [&]() {
        As[ak4 * 4 + 0][ar]      = pa0.x;
        As[ak4 * 4 + 1][ar]      = pa0.y;
        As[ak4 * 4 + 2][ar]      = pa0.z;
        As[ak4 * 4 + 3][ar]      = pa0.w;
        As[ak4 * 4 + 0][ar + 64] = pa1.x;
        As[ak4 * 4 + 1][ar + 64] = pa1.y;
        As[ak4 * 4 + 2][ar + 64] = pa1.z;
        As[ak4 * 4 + 3][ar + 64] = pa1.w;
        if (TB) {
            int c = tid >> 2, k4 = tid & 3;
            Bs[k4 * 4 + 0][c] = pb.x;
            Bs[k4 * 4 + 1][c] = pb.y;
            Bs[k4 * 4 + 2][c] = pb.z;
            Bs[k4 * 4 + 3][c] = pb.w;
        } else {
            *(float4*)&Bs[tid >> 4][(tid & 15) * 4] = pb;
        }
    };

    const int nk = K >> 4;
    loadT(0);
    storeT();
    __syncthreads();

    for (int kb = 0; kb < nk; kb++) {
        if (kb + 1 < nk) loadT(kb + 1);
#pragma unroll
        for (int kk = 0; kk < 16; kk++) {
            float4 a0 = *(const float4*)&As[kk][tyr * 8];
            float4 a1 = *(const float4*)&As[kk][tyr * 8 + 4];
            float4 b  = *(const float4*)&Bs[kk][txc * 4];
            // i-pairs come free from float4 register adjacency
            u64 ap[4] = {pack2(a0.x, a0.y), pack2(a0.z, a0.w),
                         pack2(a1.x, a1.y), pack2(a1.z, a1.w)};
            u64 bd[4] = {pack2(b.x, b.x), pack2(b.y, b.y),
                         pack2(b.z, b.z), pack2(b.w, b.w)};
#pragma unroll
            for (int i = 0; i < 4; i++)
#pragma unroll
                for (int j = 0; j < 4; j++)
                    acc2[i][j] = ffma2(ap[i], bd[j], acc2[i][j]);
        }
        __syncthreads();
        if (kb + 1 < nk) {
            storeT();
            __syncthreads();
        }
    }

    const int c = col0 + txc * 4;
    float b0 = bias[c], b1 = bias[c + 1], b2 = bias[c + 2], b3 = bias[c + 3];
#pragma unroll
    for (int ip = 0; ip < 4; ip++) {
        float2 f0 = unpack2(acc2[ip][0]);
        float2 f1 = unpack2(acc2[ip][1]);
        float2 f2 = unpack2(acc2[ip][2]);
        float2 f3 = unpack2(acc2[ip][3]);
        int r = row0 + tyr * 8 + 2 * ip;
        float4 o;
        o.x = act_fn<ACT>(f0.x + b0);
        o.y = act_fn<ACT>(f1.x + b1);
        o.z = act_fn<ACT>(f2.x + b2);
        o.w = act_fn<ACT>(f3.x + b3);
        *(float4*)&C[r * Nn + c] = o;
        o.x = act_fn<ACT>(f0.y + b0);
        o.y = act_fn<ACT>(f1.y + b1);
        o.z = act_fn<ACT>(f2.y + b2);
        o.w = act_fn<ACT>(f3.y + b3);
        *(float4*)&C[(r + 1) * Nn + c] = o;
    }
}

// ---------------- LayerNorm + residual ----------------
template <int ELU, int BASEID, int FID, int OUTID>
__global__ void __launch_bounds__(256) ln_res_kernel(
    const float* __restrict__ base_ext, float* __restrict__ out_ext,
    const float* __restrict__ gam, const float* __restrict__ bet)
{
    const float* __restrict__ base = (BASEID < 0) ? base_ext : dbuf<(BASEID < 0) ? 0 : BASEID>();
    const float* __restrict__ f = dbuf<FID>();
    float* __restrict__ out = (OUTID < 0) ? out_ext : dbuf<(OUTID < 0) ? 0 : OUTID>();

    const int r = blockIdx.x, t = threadIdx.x;
    float v = f[r * DD + t];
    __shared__ float red[8];
    __shared__ float sh_mu, sh_var;

    float s = v;
#pragma unroll
    for (int o = 16; o; o >>= 1) s += __shfl_xor_sync(0xffffffffu, s, o);
    if ((t & 31) == 0) red[t >> 5] = s;
    __syncthreads();
    if (t == 0) {
        float tot = 0.f;
#pragma unroll
        for (int i = 0; i < 8; i++) tot += red[i];
        sh_mu = tot * (1.f / 256.f);
    }
    __syncthreads();
    const float mu = sh_mu;
    const float dv = v - mu;

    s = dv * dv;
#pragma unroll
    for (int o = 16; o; o >>= 1) s += __shfl_xor_sync(0xffffffffu, s, o);
    if ((t & 31) == 0) red[t >> 5] = s;
    __syncthreads();
    if (t == 0) {
        float tot = 0.f;
#pragma unroll
        for (int i = 0; i < 8; i++) tot += red[i];
        sh_var = tot * (1.f / 256.f);
    }
    __syncthreads();

    float y = dv * rsqrtf(sh_var + 1e-5f) * gam[t] + bet[t];
    if (ELU) y = y > 0.f ? y : expm1f(y);
    out[r * DD + t] = base[r * DD + t] + y;
}

// ---------------- flash attention, split-K partials (f32x2) ------------
// grid (N/128, H, ASPLIT), 128 threads, thread = one query.
__global__ void __launch_bounds__(128) attn_part_kernel(int N)
{
    const float* __restrict__ qkv = g_qkv;

    __shared__ __align__(16) float Ks[64][36];
    __shared__ __align__(16) float Vs[64][36];
    const int h = blockIdx.y;
    const int s = blockIdx.z;
    const int t = threadIdx.x;
    const int q = blockIdx.x * 128 + t;

    u64 qr2[HDIM / 2];
    {
        const float4* qp = (const float4*)(qkv + q * (3 * DD) + h * HDIM);
#pragma unroll
        for (int i = 0; i < 8; i++) {
            float4 v = qp[i];
            qr2[2 * i + 0] = pack2(v.x, v.y);
            qr2[2 * i + 1] = pack2(v.z, v.w);
        }
    }
    u64 oo2[HDIM / 2];
#pragma unroll
    for (int i = 0; i < HDIM / 2; i++) oo2[i] = 0ull;
    float m = -1e30f, l = 0.f;
    const float sc = 0.17677669529663687f;  // 1/sqrt(32)

    const int nt = N / (64 * ASPLIT);       // key tiles per split
    const int kb0 = s * nt;
    for (int kb = kb0; kb < kb0 + nt; kb++) {
        __syncthreads();
#pragma unroll
        for (int i = 0; i < 8; i++) {
            int sl  = t + i * 128;           // 0..1023 float4 slots
            int mat = sl >> 9;               // 0 = K, 1 = V
            int rr  = (sl >> 3) & 63;        // key row
            int q4  = sl & 7;
            float4 v = *(const float4*)(qkv + (kb * 64 + rr) * (3 * DD) + DD
                                        + (mat << 8) + h * HDIM + q4 * 4);
            float* dst = (mat ? &Vs[0][0] : &Ks[0][0]) + rr * 36 + q4 * 4;
            *(float4*)dst = v;
        }
        __syncthreads();

#pragma unroll 2
        for (int j = 0; j < 64; j++) {
            const float* kr = &Ks[j][0];
            u64 s2a = 0ull, s2b = 0ull;
#pragma unroll
            for (int dd = 0; dd < 8; dd++) {
                float4 kv = *(const float4*)(kr + dd * 4);
                s2a = ffma2(qr2[2 * dd + 0], pack2(kv.x, kv.y), s2a);
                s2b = ffma2(qr2[2 * dd + 1], pack2(kv.z, kv.w), s2b);
            }
            float2 fa = unpack2(s2a), fb = unpack2(s2b);
            float sv = ((fa.x + fa.y) + (fb.x + fb.y)) * sc;
            float p;
            if (sv <= m) {
                p = __expf(sv - m);
            } else {
                float cor = __expf(m - sv);
                l *= cor;
                u64 cor2 = pack2(cor, cor);
#pragma unroll
                for (int dd = 0; dd < HDIM / 2; dd++) oo2[dd] = fmul2(oo2[dd], cor2);
                m = sv;
                p = 1.f;
            }
            l += p;
            u64 p2 = pack2(p, p);
            const float* vr = &Vs[j][0];
#pragma unroll
            for (int dd = 0; dd < 8; dd++) {
                float4 vv = *(const float4*)(vr + dd * 4);
                oo2[2 * dd + 0] = ffma2(p2, pack2(vv.x, vv.y), oo2[2 * dd + 0]);
                oo2[2 * dd + 1] = ffma2(p2, pack2(vv.z, vv.w), oo2[2 * dd + 1]);
            }
        }
    }

    const int qh = q * HH + h;
    g_ml[s * (NN * HH) + qh] = make_float2(m, l);
    float* op = g_opart + (size_t)(s * (NN * HH) + qh) * HDIM;
#pragma unroll
    for (int i = 0; i < 8; i++) {
        float2 lo = unpack2(oo2[2 * i + 0]);
        float2 hi = unpack2(oo2[2 * i + 1]);
        float4 v;
        v.x = lo.x; v.y = lo.y; v.z = hi.x; v.w = hi.y;
        *(float4*)(op + i * 4) = v;
    }
}

// Merge ASPLIT partials: standard log-sum-exp combine.
__global__ void __launch_bounds__(256) attn_reduce_kernel()
{
    const int idx = blockIdx.x * blockDim.x + threadIdx.x;  // N*H*32
    const int dd = idx & (HDIM - 1);
    const int qh = idx >> 5;  // q*H + h

    float2 ml[ASPLIT];
    float M = -1e30f;
#pragma unroll
    for (int s = 0; s < ASPLIT; s++) {
        ml[s] = g_ml[s * (NN * HH) + qh];
        M = fmaxf(M, ml[s].x);
    }
    float L = 0.f, o = 0.f;
#pragma unroll
    for (int s = 0; s < ASPLIT; s++) {
        float w = __expf(ml[s].x - M);
        L = fmaf(ml[s].y, w, L);
        o = fmaf(g_opart[(size_t)(s * (NN * HH) + qh) * HDIM + dd], w, o);
    }
    g_ao[idx] = o / L;
}

// ---------------- host launch ----------------
extern "C" void kernel_launch(void* const* d_in, const int* in_sizes, int n_in,
                              void* d_out, int out_size) {
    const float* x    = (const float*)d_in[0];
    const void*  ei   = (const void*)d_in[1];
    const float* ea   = (const float*)d_in[2];
    const float* eps  = (const float*)d_in[3];
    const float* Wl   = (const float*)d_in[4];
    const float* bl   = (const float*)d_in[5];
    const float* W1   = (const float*)d_in[6];
    const float* b1   = (const float*)d_in[7];
    const float* W2   = (const float*)d_in[8];
    const float* b2   = (const float*)d_in[9];
    const float* lnlg = (const float*)d_in[10];
    const float* lnlb = (const float*)d_in[11];
    const float* inw  = (const float*)d_in[12];
    const float* inb  = (const float*)d_in[13];
    const float* outw = (const float*)d_in[14];
    const float* outb = (const float*)d_in[15];
    const float* lnag = (const float*)d_in[16];
    const float* lnab = (const float*)d_in[17];
    const float* Wf1  = (const float*)d_in[18];
    const float* bf1  = (const float*)d_in[19];
    const float* Wf2  = (const float*)d_in[20];
    const float* bf2  = (const float*)d_in[21];
    const float* lnfg = (const float*)d_in[22];
    const float* lnfb = (const float*)d_in[23];
    float* out = (float*)d_out;

    const int E = in_sizes[1] / 2;
    const int ND = NN * DD;

    // Buffer ids: 0=agg 1=h 2=t1 3=h2 4=x1 5=qkv 6=ao 7=o2 8=x2 9=f1 10=f2

    // GINEConv: agg = segment_sum(relu(x[src] + ea@Wl + bl), dst)
    detect_idx_kernel<<<1, 1>>>((const unsigned int*)ei);
    zero_agg_kernel<<<(ND + 255) / 256, 256>>>(ND);
    gine_edge_kernel<<<(E + EPB - 1) / EPB, 256>>>(x, ei, ea, Wl, bl, E);
    combine_kernel<<<(ND + 255) / 256, 256>>>(x, eps, ND);

    // local MLP: h2 = elu(h@W1+b1)@W2+b2 ; x1 = x + elu(ln_l(h2))
    gemm_kernel<1, false, 1, 2><<<dim3(DD / 64, NN / 128), 256>>>(W1, b1, NN, DD, DD);
    gemm_kernel<0, false, 2, 3><<<dim3(DD / 64, NN / 128), 256>>>(W2, b2, NN, DD, DD);
    ln_res_kernel<1, -1, 3, 4><<<NN, 256>>>(x, nullptr, lnlg, lnlb);

    // attention: qkv = x1 @ in_w^T + in_b ; o = softmax(QK^T/sqrt(hd)) V ; proj
    gemm_kernel<0, true, 4, 5><<<dim3(3 * DD / 64, NN / 128), 256>>>(inw, inb, NN, 3 * DD, DD);
    attn_part_kernel<<<dim3(NN / 128, HH, ASPLIT), 128>>>(NN);
    attn_reduce_kernel<<<(NN * HH * HDIM) / 256, 256>>>();
    gemm_kernel<0, true, 6, 7><<<dim3(DD / 64, NN / 128), 256>>>(outw, outb, NN, DD, DD);
    ln_res_kernel<0, 4, 7, 8><<<NN, 256>>>(nullptr, nullptr, lnag, lnab);

    // FFN: f2 = gelu(x2@Wf1+bf1)@Wf2+bf2 ; out = x2 + ln_f(f2)
    gemm_kernel<2, false, 8, 9><<<dim3(2 * DD / 64, NN / 128), 256>>>(Wf1, bf1, NN, 2 * DD, DD);
    gemm_kernel<0, false, 9, 10><<<dim3(DD / 64, NN / 128), 256>>>(Wf2, bf2, NN, DD, 2 * DD);
    ln_res_kernel<0, 8, 10, -1><<<NN, 256>>>(nullptr, out, lnfg, lnfb);
}

// round 9
// speedup vs baseline: 1.5191x; 1.3082x over previous
#include <cuda_runtime.h>
#include <math.h>

// Problem constants (shapes are fixed by the reference)
#define NN 4096
#define DD 256
#define EDD 64
#define HH 8
#define HDIM 32
#define EMAX 262144
#define ASPLIT 4   // attention split-K factor

typedef unsigned long long u64;

// ---------------- packed fp32x2 helpers (attention) ----------
__device__ __forceinline__ u64 ffma2(u64 a, u64 b, u64 c) {
    u64 d;
    asm("fma.rn.f32x2 %0, %1, %2, %3;" : "=l"(d) : "l"(a), "l"(b), "l"(c));
    return d;
}
__device__ __forceinline__ u64 fmul2(u64 a, u64 b) {
    u64 d;
    asm("mul.rn.f32x2 %0, %1, %2;" : "=l"(d) : "l"(a), "l"(b));
    return d;
}
__device__ __forceinline__ u64 pack2(float lo, float hi) {
    u64 d;
    asm("mov.b64 %0, {%1, %2};" : "=l"(d) : "f"(lo), "f"(hi));
    return d;
}
__device__ __forceinline__ float2 unpack2(u64 v) {
    float2 r;
    asm("mov.b64 {%0, %1}, %2;" : "=f"(r.x), "=f"(r.y) : "l"(v));
    return r;
}
__device__ __forceinline__ unsigned cvt_tf32(float v) {
    unsigned r;
    asm("cvt.rna.tf32.f32 %0, %1;" : "=r"(r) : "f"(v));
    return r;
}

// ---------------- scratch (device globals; no allocation allowed) ----------
__device__ float g_h  [NN * DD];
__device__ float g_t1 [NN * DD];
__device__ float g_h2 [NN * DD];
__device__ float g_x1 [NN * DD];
__device__ float g_qkv[NN * 3 * DD];
__device__ float g_ao [NN * DD];
__device__ float g_o2 [NN * DD];
__device__ float g_x2 [NN * DD];
__device__ float g_f1 [NN * 2 * DD];
__device__ float g_f2 [NN * DD];
__device__ float g_T  [(size_t)EMAX * DD];          // edge lin(ea) table (256 MB)
__device__ int   g_off[NN + 1];                     // CSR offsets
__device__ int   g_cur[NN];                         // CSR fill cursors
__device__ int   g_csr_src[EMAX];
__device__ int   g_csr_eid[EMAX];
__device__ float2 g_ml[ASPLIT * NN * HH];           // (m, l) per split/query/head
__device__ float g_opart[ASPLIT * NN * HH * HDIM];  // unnormalized o per split
__device__ int   g_idx_is64;

// Compile-time scratch-buffer selector (resolved in device code).
template <int ID>
__device__ __forceinline__ float* dbuf() {
    if constexpr (ID == 1)  return g_h;
    else if constexpr (ID == 2)  return g_t1;
    else if constexpr (ID == 3)  return g_h2;
    else if constexpr (ID == 4)  return g_x1;
    else if constexpr (ID == 5)  return g_qkv;
    else if constexpr (ID == 6)  return g_ao;
    else if constexpr (ID == 7)  return g_o2;
    else if constexpr (ID == 8)  return g_x2;
    else if constexpr (ID == 9)  return g_f1;
    else if constexpr (ID == 10) return g_f2;
    else return g_T;  // 11
}

// ---------------- edge-index dtype detect ----------------
__global__ void detect_idx_kernel(const unsigned int* __restrict__ ei32) {
    unsigned int o = 0;
#pragma unroll
    for (int i = 1; i < 512; i += 2) o |= ei32[i];
    g_idx_is64 = (o == 0u) ? 1 : 0;
}

// ---------------- CSR build ----------------
__global__ void zero_off_kernel() {
    int i = blockIdx.x * blockDim.x + threadIdx.x;
    if (i < NN + 1) g_off[i] = 0;
}

__global__ void hist_kernel(const void* __restrict__ ei, int E) {
    int e = blockIdx.x * blockDim.x + threadIdx.x;
    if (e >= E) return;
    int dst = g_idx_is64 ? (int)((const long long*)ei)[E + e]
                         : ((const int*)ei)[E + e];
    dst &= NN - 1;
    atomicAdd(&g_off[dst + 1], 1);
}

// single block, 1024 threads: inclusive scan of counts g_off[1..NN]
__global__ void __launch_bounds__(1024) scan_kernel() {
    __shared__ int sm[1024];
    int t = threadIdx.x;
    int i0 = 4 * t;
    int v1 = g_off[i0 + 1], v2 = g_off[i0 + 2], v3 = g_off[i0 + 3], v4 = g_off[i0 + 4];
    int s1 = v1, s2 = s1 + v2, s3 = s2 + v3, s4 = s3 + v4;
    sm[t] = s4;
    __syncthreads();
    for (int off = 1; off < 1024; off <<= 1) {
        int add = (t >= off) ? sm[t - off] : 0;
        __syncthreads();
        sm[t] += add;
        __syncthreads();
    }
    int excl = sm[t] - s4;
    g_off[i0 + 1] = excl + s1;
    g_off[i0 + 2] = excl + s2;
    g_off[i0 + 3] = excl + s3;
    g_off[i0 + 4] = excl + s4;
    g_cur[i0 + 0] = excl;
    g_cur[i0 + 1] = excl + s1;
    g_cur[i0 + 2] = excl + s2;
    g_cur[i0 + 3] = excl + s3;
}

__global__ void fill_kernel(const void* __restrict__ ei, int E) {
    int e = blockIdx.x * blockDim.x + threadIdx.x;
    if (e >= E) return;
    int src, dst;
    if (g_idx_is64) {
        src = (int)((const long long*)ei)[e];
        dst = (int)((const long long*)ei)[E + e];
    } else {
        src = ((const int*)ei)[e];
        dst = ((const int*)ei)[E + e];
    }
    src &= NN - 1; dst &= NN - 1;
    int pos = atomicAdd(&g_cur[dst], 1);
    g_csr_src[pos] = src;
    g_csr_eid[pos] = e;
}

// ---------------- GINE aggregation (gather, no atomics) ----------------
// block = node n; thread = column d.
// g_h[n] = (1+eps)*x[n] + sum_{e: dst=n} relu(x[src_e] + T[e])
__global__ void __launch_bounds__(256) gine_aggregate_kernel(
    const float* __restrict__ x, const float* __restrict__ eps)
{
    const int n = blockIdx.x, d = threadIdx.x;
    const int s0 = g_off[n], s1 = g_off[n + 1];
    float acc = 0.f;
    int pos = s0;
    for (; pos + 2 <= s1; pos += 2) {
        int sa = g_csr_src[pos],     ea = g_csr_eid[pos];
        int sb = g_csr_src[pos + 1], eb = g_csr_eid[pos + 1];
        float va = x[sa * DD + d] + g_T[(size_t)ea * DD + d];
        float vb = x[sb * DD + d] + g_T[(size_t)eb * DD + d];
        acc += fmaxf(va, 0.f) + fmaxf(vb, 0.f);
    }
    if (pos < s1) {
        int sa = g_csr_src[pos], ea = g_csr_eid[pos];
        acc += fmaxf(x[sa * DD + d] + g_T[(size_t)ea * DD + d], 0.f);
    }
    g_h[n * DD + d] = (1.f + eps[0]) * x[n * DD + d] + acc;
}

// ---------------- tf32 tensor-core GEMM ----------------
// C[M,Nn] = act(A@B + bias); B normal [K,Nn] or TB: [Nn,K] (C=A@B^T).
// BM=128, BN=64, BK=16, 256 threads (8 warps), warp = 16 rows x 64 cols.
// mma.sync.m16n8k8 tf32, fp32 accumulate, cvt.rna on smem store.
template <int ACT>
__device__ __forceinline__ float act_fn(float v) {
    if (ACT == 1) return v > 0.f ? v : expm1f(v);                           // ELU
    if (ACT == 2) return 0.5f * v * (1.f + erff(v * 0.7071067811865476f));  // exact GELU
    return v;
}

__device__ __forceinline__ void mma_tf32(float c[4], unsigned a0, unsigned a1,
                                         unsigned a2, unsigned a3,
                                         unsigned b0, unsigned b1) {
    asm("mma.sync.aligned.m16n8k8.row.col.f32.tf32.tf32.f32 "
        "{%0,%1,%2,%3}, {%4,%5,%6,%7}, {%8,%9}, {%0,%1,%2,%3};"
        : "+f"(c[0]), "+f"(c[1]), "+f"(c[2]), "+f"(c[3])
        : "r"(a0), "r"(a1), "r"(a2), "r"(a3), "r"(b0), "r"(b1));
}

template <int ACT, bool TB, int AID, int CID>
__global__ void __launch_bounds__(256) gemm_tf32_kernel(
    const float* __restrict__ Aext, const float* __restrict__ B,
    const float* __restrict__ bias, int M, int Nn, int K)
{
    const float* __restrict__ A = (AID < 0) ? Aext : dbuf<(AID < 0) ? 1 : AID>();
    float* __restrict__ C = dbuf<CID>();

    __shared__ unsigned As[16][136];  // [k][m], stride 136 -> conflict-free frags
    __shared__ unsigned Bs[16][72];   // [k][n]

    const int tid  = threadIdx.x;
    const int wid  = tid >> 5;
    const int lane = tid & 31;
    const int row0 = blockIdx.x * 128;
    const int col0 = blockIdx.y * 64;

    const int ar  = tid >> 2;   // 0..63 A row within half-tile
    const int ak4 = tid & 3;    // which float4 along k

    float4 pa0, pa1, pb;
    float acc[8][4];
#pragma unroll
    for (int j = 0; j < 8; j++)
#pragma unroll
        for (int i = 0; i < 4; i++) acc[j][i] = 0.f;

    auto loadT = [&](int kb) {
        const float* Ab = A + (size_t)(row0) * K + kb * 16;
        pa0 = *(const float4*)(Ab + (size_t)(ar)      * K + ak4 * 4);
        pa1 = *(const float4*)(Ab + (size_t)(ar + 64) * K + ak4 * 4);
        if (TB) {
            const float* Bb = B + col0 * K + kb * 16;
            pb = *(const float4*)(Bb + (tid >> 2) * K + (tid & 3) * 4);
        } else {
            const float* Bb = B + (kb * 16) * Nn + col0;
            pb = *(const float4*)(Bb + (tid >> 4) * Nn + (tid & 15) * 4);
        }
    };
    auto storeT = [&]() {
        As[ak4 * 4 + 0][ar]      = cvt_tf32(pa0.x);
        As[ak4 * 4 + 1][ar]      = cvt_tf32(pa0.y);
        As[ak4 * 4 + 2][ar]      = cvt_tf32(pa0.z);
        As[ak4 * 4 + 3][ar]      = cvt_tf32(pa0.w);
        As[ak4 * 4 + 0][ar + 64] = cvt_tf32(pa1.x);
        As[ak4 * 4 + 1][ar + 64] = cvt_tf32(pa1.y);
        As[ak4 * 4 + 2][ar + 64] = cvt_tf32(pa1.z);
        As[ak4 * 4 + 3][ar + 64] = cvt_tf32(pa1.w);
        if (TB) {
            int c = tid >> 2, k4 = tid & 3;
            Bs[k4 * 4 + 0][c] = cvt_tf32(pb.x);
            Bs[k4 * 4 + 1][c] = cvt_tf32(pb.y);
            Bs[k4 * 4 + 2][c] = cvt_tf32(pb.z);
            Bs[k4 * 4 + 3][c] = cvt_tf32(pb.w);
        } else {
            int kr = tid >> 4, c = (tid & 15) * 4;
            Bs[kr][c + 0] = cvt_tf32(pb.x);
            Bs[kr][c + 1] = cvt_tf32(pb.y);
            Bs[kr][c + 2] = cvt_tf32(pb.z);
            Bs[kr][c + 3] = cvt_tf32(pb.w);
        }
    };

    const int nk = K >> 4;
    loadT(0);
    storeT();
    __syncthreads();

    const int m0  = wid * 16;
    const int row = lane >> 2;
    const int kq  = lane & 3;

    for (int kb = 0; kb < nk; kb++) {
        if (kb + 1 < nk) loadT(kb + 1);
#pragma unroll
        for (int k0 = 0; k0 < 16; k0 += 8) {
            unsigned a0 = As[k0 + kq][m0 + row];
            unsigned a1 = As[k0 + kq][m0 + row + 8];
            unsigned a2 = As[k0 + kq + 4][m0 + row];
            unsigned a3 = As[k0 + kq + 4][m0 + row + 8];
#pragma unroll
            for (int j = 0; j < 8; j++) {
                unsigned b0 = Bs[k0 + kq][j * 8 + row];
                unsigned b1 = Bs[k0 + kq + 4][j * 8 + row];
                mma_tf32(acc[j], a0, a1, a2, a3, b0, b1);
            }
        }
        __syncthreads();
        if (kb + 1 < nk) {
            storeT();
            __syncthreads();
        }
    }

    // epilogue: c0->(row, 2q), c1->(row, 2q+1), c2->(row+8, 2q), c3->(row+8, 2q+1)
    const int col2 = (lane & 3) * 2;
    const size_t r0 = (size_t)(row0 + m0 + row);
#pragma unroll
    for (int j = 0; j < 8; j++) {
        int n = col0 + j * 8 + col2;
        float bv0 = bias[n], bv1 = bias[n + 1];
        float2 lo, hi;
        lo.x = act_fn<ACT>(acc[j][0] + bv0);
        lo.y = act_fn<ACT>(acc[j][1] + bv1);
        hi.x = act_fn<ACT>(acc[j][2] + bv0);
        hi.y = act_fn<ACT>(acc[j][3] + bv1);
        *(float2*)&C[r0 * Nn + n] = lo;
        *(float2*)&C[(r0 + 8) * Nn + n] = hi;
    }
}

// ---------------- LayerNorm + residual ----------------
template <int ELU, int BASEID, int FID, int OUTID>
__global__ void __launch_bounds__(256) ln_res_kernel(
    const float* __restrict__ base_ext, float* __restrict__ out_ext,
    const float* __restrict__ gam, const float* __restrict__ bet)
{
    const float* __restrict__ base = (BASEID < 0) ? base_ext : dbuf<(BASEID < 0) ? 1 : BASEID>();
    const float* __restrict__ f = dbuf<FID>();
    float* __restrict__ out = (OUTID < 0) ? out_ext : dbuf<(OUTID < 0) ? 1 : OUTID>();

    const int r = blockIdx.x, t = threadIdx.x;
    float v = f[r * DD + t];
    __shared__ float red[8];
    __shared__ float sh_mu, sh_var;

    float s = v;
#pragma unroll
    for (int o = 16; o; o >>= 1) s += __shfl_xor_sync(0xffffffffu, s, o);
    if ((t & 31) == 0) red[t >> 5] = s;
    __syncthreads();
    if (t == 0) {
        float tot = 0.f;
#pragma unroll
        for (int i = 0; i < 8; i++) tot += red[i];
        sh_mu = tot * (1.f / 256.f);
    }
    __syncthreads();
    const float mu = sh_mu;
    const float dv = v - mu;

    s = dv * dv;
#pragma unroll
    for (int o = 16; o; o >>= 1) s += __shfl_xor_sync(0xffffffffu, s, o);
    if ((t & 31) == 0) red[t >> 5] = s;
    __syncthreads();
    if (t == 0) {
        float tot = 0.f;
#pragma unroll
        for (int i = 0; i < 8; i++) tot += red[i];
        sh_var = tot * (1.f / 256.f);
    }
    __syncthreads();

    float y = dv * rsqrtf(sh_var + 1e-5f) * gam[t] + bet[t];
    if (ELU) y = y > 0.f ? y : expm1f(y);
    out[r * DD + t] = base[r * DD + t] + y;
}

// ---------------- flash attention, split-K partials (f32x2) ------------
__global__ void __launch_bounds__(128) attn_part_kernel(int N)
{
    const float* __restrict__ qkv = g_qkv;

    __shared__ __align__(16) float Ks[64][36];
    __shared__ __align__(16) float Vs[64][36];
    const int h = blockIdx.y;
    const int s = blockIdx.z;
    const int t = threadIdx.x;
    const int q = blockIdx.x * 128 + t;

    u64 qr2[HDIM / 2];
    {
        const float4* qp = (const float4*)(qkv + q * (3 * DD) + h * HDIM);
#pragma unroll
        for (int i = 0; i < 8; i++) {
            float4 v = qp[i];
            qr2[2 * i + 0] = pack2(v.x, v.y);
            qr2[2 * i + 1] = pack2(v.z, v.w);
        }
    }
    u64 oo2[HDIM / 2];
#pragma unroll
    for (int i = 0; i < HDIM / 2; i++) oo2[i] = 0ull;
    float m = -1e30f, l = 0.f;
    const float sc = 0.17677669529663687f;  // 1/sqrt(32)

    const int nt = N / (64 * ASPLIT);
    const int kb0 = s * nt;
    for (int kb = kb0; kb < kb0 + nt; kb++) {
        __syncthreads();
#pragma unroll
        for (int i = 0; i < 8; i++) {
            int sl  = t + i * 128;
            int mat = sl >> 9;
            int rr  = (sl >> 3) & 63;
            int q4  = sl & 7;
            float4 v = *(const float4*)(qkv + (kb * 64 + rr) * (3 * DD) + DD
                                        + (mat << 8) + h * HDIM + q4 * 4);
            float* dst = (mat ? &Vs[0][0] : &Ks[0][0]) + rr * 36 + q4 * 4;
            *(float4*)dst = v;
        }
        __syncthreads();

#pragma unroll 2
        for (int j = 0; j < 64; j++) {
            const float* kr = &Ks[j][0];
            u64 s2a = 0ull, s2b = 0ull;
#pragma unroll
            for (int dd = 0; dd < 8; dd++) {
                float4 kv = *(const float4*)(kr + dd * 4);
                s2a = ffma2(qr2[2 * dd + 0], pack2(kv.x, kv.y), s2a);
                s2b = ffma2(qr2[2 * dd + 1], pack2(kv.z, kv.w), s2b);
            }
            float2 fa = unpack2(s2a), fb = unpack2(s2b);
            float sv = ((fa.x + fa.y) + (fb.x + fb.y)) * sc;
            float p;
            if (sv <= m) {
                p = __expf(sv - m);
            } else {
                float cor = __expf(m - sv);
                l *= cor;
                u64 cor2 = pack2(cor, cor);
#pragma unroll
                for (int dd = 0; dd < HDIM / 2; dd++) oo2[dd] = fmul2(oo2[dd], cor2);
                m = sv;
                p = 1.f;
            }
            l += p;
            u64 p2 = pack2(p, p);
            const float* vr = &Vs[j][0];
#pragma unroll
            for (int dd = 0; dd < 8; dd++) {
                float4 vv = *(const float4*)(vr + dd * 4);
                oo2[2 * dd + 0] = ffma2(p2, pack2(vv.x, vv.y), oo2[2 * dd + 0]);
                oo2[2 * dd + 1] = ffma2(p2, pack2(vv.z, vv.w), oo2[2 * dd + 1]);
            }
        }
    }

    const int qh = q * HH + h;
    g_ml[s * (NN * HH) + qh] = make_float2(m, l);
    float* op = g_opart + (size_t)(s * (NN * HH) + qh) * HDIM;
#pragma unroll
    for (int i = 0; i < 8; i++) {
        float2 lo = unpack2(oo2[2 * i + 0]);
        float2 hi = unpack2(oo2[2 * i + 1]);
        float4 v;
        v.x = lo.x; v.y = lo.y; v.z = hi.x; v.w = hi.y;
        *(float4*)(op + i * 4) = v;
    }
}

__global__ void __launch_bounds__(256) attn_reduce_kernel()
{
    const int idx = blockIdx.x * blockDim.x + threadIdx.x;  // N*H*32
    const int dd = idx & (HDIM - 1);
    const int qh = idx >> 5;

    float2 ml[ASPLIT];
    float M = -1e30f;
#pragma unroll
    for (int s = 0; s < ASPLIT; s++) {
        ml[s] = g_ml[s * (NN * HH) + qh];
        M = fmaxf(M, ml[s].x);
    }
    float L = 0.f, o = 0.f;
#pragma unroll
    for (int s = 0; s < ASPLIT; s++) {
        float w = __expf(ml[s].x - M);
        L = fmaf(ml[s].y, w, L);
        o = fmaf(g_opart[(size_t)(s * (NN * HH) + qh) * HDIM + dd], w, o);
    }
    g_ao[idx] = o / L;
}

// ---------------- host launch ----------------
extern "C" void kernel_launch(void* const* d_in, const int* in_sizes, int n_in,
                              void* d_out, int out_size) {
    const float* x    = (const float*)d_in[0];
    const void*  ei   = (const void*)d_in[1];
    const float* ea   = (const float*)d_in[2];
    const float* eps  = (const float*)d_in[3];
    const float* Wl   = (const float*)d_in[4];
    const float* bl   = (const float*)d_in[5];
    const float* W1   = (const float*)d_in[6];
    const float* b1   = (const float*)d_in[7];
    const float* W2   = (const float*)d_in[8];
    const float* b2   = (const float*)d_in[9];
    const float* lnlg = (const float*)d_in[10];
    const float* lnlb = (const float*)d_in[11];
    const float* inw  = (const float*)d_in[12];
    const float* inb  = (const float*)d_in[13];
    const float* outw = (const float*)d_in[14];
    const float* outb = (const float*)d_in[15];
    const float* lnag = (const float*)d_in[16];
    const float* lnab = (const float*)d_in[17];
    const float* Wf1  = (const float*)d_in[18];
    const float* bf1  = (const float*)d_in[19];
    const float* Wf2  = (const float*)d_in[20];
    const float* bf2  = (const float*)d_in[21];
    const float* lnfg = (const float*)d_in[22];
    const float* lnfb = (const float*)d_in[23];
    float* out = (float*)d_out;

    const int E = in_sizes[1] / 2;

    // Buffer ids: 1=h 2=t1 3=h2 4=x1 5=qkv 6=ao 7=o2 8=x2 9=f1 10=f2 11=T

    // ---- GINEConv (CSR gather, tensor-core edge GEMM, zero float atomics)
    detect_idx_kernel<<<1, 1>>>((const unsigned int*)ei);
    zero_off_kernel<<<(NN + 256) / 256, 256>>>();
    hist_kernel<<<(E + 255) / 256, 256>>>(ei, E);
    scan_kernel<<<1, 1024>>>();
    fill_kernel<<<(E + 255) / 256, 256>>>(ei, E);
    // T = ea @ Wl + bl  (E x 256 from K=64)
    gemm_tf32_kernel<0, false, -1, 11><<<dim3(E / 128, DD / 64), 256>>>(ea, Wl, bl, E, DD, EDD);
    gine_aggregate_kernel<<<NN, 256>>>(x, eps);

    // ---- local MLP: h2 = elu(h@W1+b1)@W2+b2 ; x1 = x + elu(ln_l(h2))
    gemm_tf32_kernel<1, false, 1, 2><<<dim3(NN / 128, DD / 64), 256>>>(nullptr, W1, b1, NN, DD, DD);
    gemm_tf32_kernel<0, false, 2, 3><<<dim3(NN / 128, DD / 64), 256>>>(nullptr, W2, b2, NN, DD, DD);
    ln_res_kernel<1, -1, 3, 4><<<NN, 256>>>(x, nullptr, lnlg, lnlb);

    // ---- attention
    gemm_tf32_kernel<0, true, 4, 5><<<dim3(NN / 128, 3 * DD / 64), 256>>>(nullptr, inw, inb, NN, 3 * DD, DD);
    attn_part_kernel<<<dim3(NN / 128, HH, ASPLIT), 128>>>(NN);
    attn_reduce_kernel<<<(NN * HH * HDIM) / 256, 256>>>();
    gemm_tf32_kernel<0, true, 6, 7><<<dim3(NN / 128, DD / 64), 256>>>(nullptr, outw, outb, NN, DD, DD);
    ln_res_kernel<0, 4, 7, 8><<<NN, 256>>>(nullptr, nullptr, lnag, lnab);

    // ---- FFN
    gemm_tf32_kernel<2, false, 8, 9><<<dim3(NN / 128, 2 * DD / 64), 256>>>(nullptr, Wf1, bf1, NN, 2 * DD, DD);
    gemm_tf32_kernel<0, false, 9, 10><<<dim3(NN / 128, DD / 64), 256>>>(nullptr, Wf2, bf2, NN, DD, 2 * DD);
    ln_res_kernel<0, 8, 10, -1><<<NN, 256>>>(nullptr, out, lnfg, lnfb);
}

// round 10
// speedup vs baseline: 2.2582x; 1.4865x over previous
#include <cuda_runtime.h>
#include <math.h>

// Problem constants (shapes are fixed by the reference)
#define NN 4096
#define DD 256
#define EDD 64
#define HH 8
#define HDIM 32
#define EMAX 262144
#define ASPLIT 2   // attention split-K factor
#define QT 64      // attention queries per block
#define KT 64      // attention keys per tile

// ---------------- helpers ----------------
__device__ __forceinline__ unsigned cvt_tf32(float v) {
    unsigned r;
    asm("cvt.rna.tf32.f32 %0, %1;" : "=r"(r) : "f"(v));
    return r;
}
__device__ __forceinline__ void mma_tf32(float c[4], unsigned a0, unsigned a1,
                                         unsigned a2, unsigned a3,
                                         unsigned b0, unsigned b1) {
    asm("mma.sync.aligned.m16n8k8.row.col.f32.tf32.tf32.f32 "
        "{%0,%1,%2,%3}, {%4,%5,%6,%7}, {%8,%9}, {%0,%1,%2,%3};"
        : "+f"(c[0]), "+f"(c[1]), "+f"(c[2]), "+f"(c[3])
        : "r"(a0), "r"(a1), "r"(a2), "r"(a3), "r"(b0), "r"(b1));
}

// ---------------- scratch (device globals; no allocation allowed) ----------
__device__ float g_h  [NN * DD];
__device__ float g_t1 [NN * DD];
__device__ float g_h2 [NN * DD];
__device__ float g_x1 [NN * DD];
__device__ float g_qkv[NN * 3 * DD];
__device__ float g_ao [NN * DD];
__device__ float g_o2 [NN * DD];
__device__ float g_x2 [NN * DD];
__device__ float g_f1 [NN * 2 * DD];
__device__ float g_f2 [NN * DD];
__device__ float g_T  [(size_t)EMAX * DD];          // edge lin(ea) table (256 MB)
__device__ int   g_off[NN + 1];                     // CSR offsets
__device__ int   g_cur[NN];                         // CSR fill cursors
__device__ int   g_csr_src[EMAX];
__device__ int   g_csr_eid[EMAX];
__device__ float2 g_ml[ASPLIT * NN * HH];           // (m, l) per split/query/head
__device__ float g_opart[ASPLIT * NN * HH * HDIM];  // unnormalized o per split
__device__ int   g_idx_is64;

// Compile-time scratch-buffer selector (resolved in device code).
template <int ID>
__device__ __forceinline__ float* dbuf() {
    if constexpr (ID == 1)  return g_h;
    else if constexpr (ID == 2)  return g_t1;
    else if constexpr (ID == 3)  return g_h2;
    else if constexpr (ID == 4)  return g_x1;
    else if constexpr (ID == 5)  return g_qkv;
    else if constexpr (ID == 6)  return g_ao;
    else if constexpr (ID == 7)  return g_o2;
    else if constexpr (ID == 8)  return g_x2;
    else if constexpr (ID == 9)  return g_f1;
    else if constexpr (ID == 10) return g_f2;
    else return g_T;  // 11
}

// ---------------- edge-index dtype detect ----------------
__global__ void detect_idx_kernel(const unsigned int* __restrict__ ei32) {
    unsigned int o = 0;
#pragma unroll
    for (int i = 1; i < 512; i += 2) o |= ei32[i];
    g_idx_is64 = (o == 0u) ? 1 : 0;
}

// ---------------- CSR build ----------------
__global__ void zero_off_kernel() {
    int i = blockIdx.x * blockDim.x + threadIdx.x;
    if (i < NN + 1) g_off[i] = 0;
}

__global__ void hist_kernel(const void* __restrict__ ei, int E) {
    int e = blockIdx.x * blockDim.x + threadIdx.x;
    if (e >= E) return;
    int dst = g_idx_is64 ? (int)((const long long*)ei)[E + e]
                         : ((const int*)ei)[E + e];
    dst &= NN - 1;
    atomicAdd(&g_off[dst + 1], 1);
}

// single block, 1024 threads: inclusive scan of counts g_off[1..NN]
__global__ void __launch_bounds__(1024) scan_kernel() {
    __shared__ int sm[1024];
    int t = threadIdx.x;
    int i0 = 4 * t;
    int v1 = g_off[i0 + 1], v2 = g_off[i0 + 2], v3 = g_off[i0 + 3], v4 = g_off[i0 + 4];
    int s1 = v1, s2 = s1 + v2, s3 = s2 + v3, s4 = s3 + v4;
    sm[t] = s4;
    __syncthreads();
    for (int off = 1; off < 1024; off <<= 1) {
        int add = (t >= off) ? sm[t - off] : 0;
        __syncthreads();
        sm[t] += add;
        __syncthreads();
    }
    int excl = sm[t] - s4;
    g_off[i0 + 1] = excl + s1;
    g_off[i0 + 2] = excl + s2;
    g_off[i0 + 3] = excl + s3;
    g_off[i0 + 4] = excl + s4;
    g_cur[i0 + 0] = excl;
    g_cur[i0 + 1] = excl + s1;
    g_cur[i0 + 2] = excl + s2;
    g_cur[i0 + 3] = excl + s3;
}

__global__ void fill_kernel(const void* __restrict__ ei, int E) {
    int e = blockIdx.x * blockDim.x + threadIdx.x;
    if (e >= E) return;
    int src, dst;
    if (g_idx_is64) {
        src = (int)((const long long*)ei)[e];
        dst = (int)((const long long*)ei)[E + e];
    } else {
        src = ((const int*)ei)[e];
        dst = ((const int*)ei)[E + e];
    }
    src &= NN - 1; dst &= NN - 1;
    int pos = atomicAdd(&g_cur[dst], 1);
    g_csr_src[pos] = src;
    g_csr_eid[pos] = e;
}

// ---------------- GINE aggregation (gather, no atomics) ----------------
__global__ void __launch_bounds__(256) gine_aggregate_kernel(
    const float* __restrict__ x, const float* __restrict__ eps)
{
    const int n = blockIdx.x, d = threadIdx.x;
    const int s0 = g_off[n], s1 = g_off[n + 1];
    float acc = 0.f;
    int pos = s0;
    for (; pos + 2 <= s1; pos += 2) {
        int sa = g_csr_src[pos],     ea = g_csr_eid[pos];
        int sb = g_csr_src[pos + 1], eb = g_csr_eid[pos + 1];
        float va = x[sa * DD + d] + g_T[(size_t)ea * DD + d];
        float vb = x[sb * DD + d] + g_T[(size_t)eb * DD + d];
        acc += fmaxf(va, 0.f) + fmaxf(vb, 0.f);
    }
    if (pos < s1) {
        int sa = g_csr_src[pos], ea = g_csr_eid[pos];
        acc += fmaxf(x[sa * DD + d] + g_T[(size_t)ea * DD + d], 0.f);
    }
    g_h[n * DD + d] = (1.f + eps[0]) * x[n * DD + d] + acc;
}

// ---------------- tf32 tensor-core GEMM ----------------
template <int ACT>
__device__ __forceinline__ float act_fn(float v) {
    if (ACT == 1) return v > 0.f ? v : expm1f(v);                           // ELU
    if (ACT == 2) return 0.5f * v * (1.f + erff(v * 0.7071067811865476f));  // exact GELU
    return v;
}

template <int ACT, bool TB, int AID, int CID>
__global__ void __launch_bounds__(256) gemm_tf32_kernel(
    const float* __restrict__ Aext, const float* __restrict__ B,
    const float* __restrict__ bias, int M, int Nn, int K)
{
    const float* __restrict__ A = (AID < 0) ? Aext : dbuf<(AID < 0) ? 1 : AID>();
    float* __restrict__ C = dbuf<CID>();

    __shared__ unsigned As[16][136];
    __shared__ unsigned Bs[16][72];

    const int tid  = threadIdx.x;
    const int wid  = tid >> 5;
    const int lane = tid & 31;
    const int row0 = blockIdx.x * 128;
    const int col0 = blockIdx.y * 64;

    const int ar  = tid >> 2;
    const int ak4 = tid & 3;

    float4 pa0, pa1, pb;
    float acc[8][4];
#pragma unroll
    for (int j = 0; j < 8; j++)
#pragma unroll
        for (int i = 0; i < 4; i++) acc[j][i] = 0.f;

    auto loadT = [&](int kb) {
        const float* Ab = A + (size_t)(row0) * K + kb * 16;
        pa0 = *(const float4*)(Ab + (size_t)(ar)      * K + ak4 * 4);
        pa1 = *(const float4*)(Ab + (size_t)(ar + 64) * K + ak4 * 4);
        if (TB) {
            const float* Bb = B + col0 * K + kb * 16;
            pb = *(const float4*)(Bb + (tid >> 2) * K + (tid & 3) * 4);
        } else {
            const float* Bb = B + (kb * 16) * Nn + col0;
            pb = *(const float4*)(Bb + (tid >> 4) * Nn + (tid & 15) * 4);
        }
    };
    auto storeT = [&]() {
        As[ak4 * 4 + 0][ar]      = cvt_tf32(pa0.x);
        As[ak4 * 4 + 1][ar]      = cvt_tf32(pa0.y);
        As[ak4 * 4 + 2][ar]      = cvt_tf32(pa0.z);
        As[ak4 * 4 + 3][ar]      = cvt_tf32(pa0.w);
        As[ak4 * 4 + 0][ar + 64] = cvt_tf32(pa1.x);
        As[ak4 * 4 + 1][ar + 64] = cvt_tf32(pa1.y);
        As[ak4 * 4 + 2][ar + 64] = cvt_tf32(pa1.z);
        As[ak4 * 4 + 3][ar + 64] = cvt_tf32(pa1.w);
        if (TB) {
            int c = tid >> 2, k4 = tid & 3;
            Bs[k4 * 4 + 0][c] = cvt_tf32(pb.x);
            Bs[k4 * 4 + 1][c] = cvt_tf32(pb.y);
            Bs[k4 * 4 + 2][c] = cvt_tf32(pb.z);
            Bs[k4 * 4 + 3][c] = cvt_tf32(pb.w);
        } else {
            int kr = tid >> 4, c = (tid & 15) * 4;
            Bs[kr][c + 0] = cvt_tf32(pb.x);
            Bs[kr][c + 1] = cvt_tf32(pb.y);
            Bs[kr][c + 2] = cvt_tf32(pb.z);
            Bs[kr][c + 3] = cvt_tf32(pb.w);
        }
    };

    const int nk = K >> 4;
    loadT(0);
    storeT();
    __syncthreads();

    const int m0  = wid * 16;
    const int row = lane >> 2;
    const int kq  = lane & 3;

    for (int kb = 0; kb < nk; kb++) {
        if (kb + 1 < nk) loadT(kb + 1);
#pragma unroll
        for (int k0 = 0; k0 < 16; k0 += 8) {
            unsigned a0 = As[k0 + kq][m0 + row];
            unsigned a1 = As[k0 + kq][m0 + row + 8];
            unsigned a2 = As[k0 + kq + 4][m0 + row];
            unsigned a3 = As[k0 + kq + 4][m0 + row + 8];
#pragma unroll
            for (int j = 0; j < 8; j++) {
                unsigned b0 = Bs[k0 + kq][j * 8 + row];
                unsigned b1 = Bs[k0 + kq + 4][j * 8 + row];
                mma_tf32(acc[j], a0, a1, a2, a3, b0, b1);
            }
        }
        __syncthreads();
        if (kb + 1 < nk) {
            storeT();
            __syncthreads();
        }
    }

    const int col2 = (lane & 3) * 2;
    const size_t r0 = (size_t)(row0 + m0 + row);
#pragma unroll
    for (int j = 0; j < 8; j++) {
        int n = col0 + j * 8 + col2;
        float bv0 = bias[n], bv1 = bias[n + 1];
        float2 lo, hi;
        lo.x = act_fn<ACT>(acc[j][0] + bv0);
        lo.y = act_fn<ACT>(acc[j][1] + bv1);
        hi.x = act_fn<ACT>(acc[j][2] + bv0);
        hi.y = act_fn<ACT>(acc[j][3] + bv1);
        *(float2*)&C[r0 * Nn + n] = lo;
        *(float2*)&C[(r0 + 8) * Nn + n] = hi;
    }
}

// ---------------- LayerNorm + residual ----------------
template <int ELU, int BASEID, int FID, int OUTID>
__global__ void __launch_bounds__(256) ln_res_kernel(
    const float* __restrict__ base_ext, float* __restrict__ out_ext,
    const float* __restrict__ gam, const float* __restrict__ bet)
{
    const float* __restrict__ base = (BASEID < 0) ? base_ext : dbuf<(BASEID < 0) ? 1 : BASEID>();
    const float* __restrict__ f = dbuf<FID>();
    float* __restrict__ out = (OUTID < 0) ? out_ext : dbuf<(OUTID < 0) ? 1 : OUTID>();

    const int r = blockIdx.x, t = threadIdx.x;
    float v = f[r * DD + t];
    __shared__ float red[8];
    __shared__ float sh_mu, sh_var;

    float s = v;
#pragma unroll
    for (int o = 16; o; o >>= 1) s += __shfl_xor_sync(0xffffffffu, s, o);
    if ((t & 31) == 0) red[t >> 5] = s;
    __syncthreads();
    if (t == 0) {
        float tot = 0.f;
#pragma unroll
        for (int i = 0; i < 8; i++) tot += red[i];
        sh_mu = tot * (1.f / 256.f);
    }
    __syncthreads();
    const float mu = sh_mu;
    const float dv = v - mu;

    s = dv * dv;
#pragma unroll
    for (int o = 16; o; o >>= 1) s += __shfl_xor_sync(0xffffffffu, s, o);
    if ((t & 31) == 0) red[t >> 5] = s;
    __syncthreads();
    if (t == 0) {
        float tot = 0.f;
#pragma unroll
        for (int i = 0; i < 8; i++) tot += red[i];
        sh_var = tot * (1.f / 256.f);
    }
    __syncthreads();

    float y = dv * rsqrtf(sh_var + 1e-5f) * gam[t] + bet[t];
    if (ELU) y = y > 0.f ? y : expm1f(y);
    out[r * DD + t] = base[r * DD + t] + y;
}

// ---------------- flash attention via mma (tf32 QK/PV, fp32 softmax) ----
// grid (NN/QT, HH, ASPLIT); 128 threads = 4 warps; warp owns 16 query rows.
// Emits unnormalized split partials into g_ml / g_opart.
__global__ void __launch_bounds__(128) attn_mma_kernel(int N)
{
    __shared__ __align__(16) unsigned Ks[KT][36];
    __shared__ __align__(16) unsigned Vs[KT][36];
    __shared__ __align__(16) unsigned Ps[4][16][68];

    const int h = blockIdx.y;
    const int sp = blockIdx.z;
    const int t = threadIdx.x;
    const int w = t >> 5, lane = t & 31;
    const int g = lane >> 2, q4 = lane & 3;
    const int q0 = blockIdx.x * QT;
    const int r0 = w * 16 + g;   // warp-local query row (and +8)

    // ---- stage Q tile [64][32] (fp32) into Ks region, then build A-frags
    {
        float* Qs = (float*)&Ks[0][0];  // viewed as [64][36] floats
        for (int i = t; i < QT * 8; i += 128) {
            int row = i >> 3, c4 = (i & 7) * 4;
            float4 v = *(const float4*)(g_qkv + (size_t)(q0 + row) * 768 + h * HDIM + c4);
            *(float4*)(Qs + row * 36 + c4) = v;
        }
    }
    __syncthreads();
    unsigned qa[4][4];
    {
        const float sc = 0.17677669529663687f;  // 1/sqrt(32), pre-folded into Q
        const float* Qs = (const float*)&Ks[0][0];
#pragma unroll
        for (int kc = 0; kc < 4; kc++) {
            qa[kc][0] = cvt_tf32(Qs[(r0)     * 36 + kc * 8 + q4]     * sc);
            qa[kc][1] = cvt_tf32(Qs[(r0 + 8) * 36 + kc * 8 + q4]     * sc);
            qa[kc][2] = cvt_tf32(Qs[(r0)     * 36 + kc * 8 + q4 + 4] * sc);
            qa[kc][3] = cvt_tf32(Qs[(r0 + 8) * 36 + kc * 8 + q4 + 4] * sc);
        }
    }

    float o[4][4];
#pragma unroll
    for (int nt = 0; nt < 4; nt++)
#pragma unroll
        for (int i = 0; i < 4; i++) o[nt][i] = 0.f;
    float m0 = -1e30f, m1 = -1e30f, l0 = 0.f, l1 = 0.f;

    const int ntile = N / (KT * ASPLIT);
    const int kb0 = sp * ntile;
    for (int kb = kb0; kb < kb0 + ntile; kb++) {
        __syncthreads();  // previous tile's Ks/Vs reads done
        // ---- stage K/V tile [64 keys][32 dims], tf32-cvt at store
        for (int i = t; i < KT * 8; i += 128) {
            int row = i >> 3, c4 = (i & 7) * 4;
            const float* bp = g_qkv + (size_t)(kb * KT + row) * 768 + DD + h * HDIM + c4;
            float4 kv = *(const float4*)bp;
            float4 vv = *(const float4*)(bp + DD);
            Ks[row][c4 + 0] = cvt_tf32(kv.x);
            Ks[row][c4 + 1] = cvt_tf32(kv.y);
            Ks[row][c4 + 2] = cvt_tf32(kv.z);
            Ks[row][c4 + 3] = cvt_tf32(kv.w);
            Vs[row][c4 + 0] = cvt_tf32(vv.x);
            Vs[row][c4 + 1] = cvt_tf32(vv.y);
            Vs[row][c4 + 2] = cvt_tf32(vv.z);
            Vs[row][c4 + 3] = cvt_tf32(vv.w);
        }
        __syncthreads();

        // ---- QK^T: scores c[j][4], j = 8-key tile
        float c[8][4];
#pragma unroll
        for (int j = 0; j < 8; j++)
#pragma unroll
            for (int i = 0; i < 4; i++) c[j][i] = 0.f;
#pragma unroll
        for (int kc = 0; kc < 4; kc++) {
#pragma unroll
            for (int j = 0; j < 8; j++) {
                unsigned b0 = Ks[j * 8 + g][kc * 8 + q4];
                unsigned b1 = Ks[j * 8 + g][kc * 8 + q4 + 4];
                mma_tf32(c[j], qa[kc][0], qa[kc][1], qa[kc][2], qa[kc][3], b0, b1);
            }
        }

        // ---- online softmax (rows r0 and r0+8, quad-cooperative)
        float rm0 = -1e30f, rm1 = -1e30f;
#pragma unroll
        for (int j = 0; j < 8; j++) {
            rm0 = fmaxf(rm0, fmaxf(c[j][0], c[j][1]));
            rm1 = fmaxf(rm1, fmaxf(c[j][2], c[j][3]));
        }
        rm0 = fmaxf(rm0, __shfl_xor_sync(0xffffffffu, rm0, 1));
        rm0 = fmaxf(rm0, __shfl_xor_sync(0xffffffffu, rm0, 2));
        rm1 = fmaxf(rm1, __shfl_xor_sync(0xffffffffu, rm1, 1));
        rm1 = fmaxf(rm1, __shfl_xor_sync(0xffffffffu, rm1, 2));
        float m0n = fmaxf(m0, rm0), m1n = fmaxf(m1, rm1);
        float cor0 = __expf(m0 - m0n), cor1 = __expf(m1 - m1n);
        l0 *= cor0; l1 *= cor1;
#pragma unroll
        for (int nt = 0; nt < 4; nt++) {
            o[nt][0] *= cor0; o[nt][1] *= cor0;
            o[nt][2] *= cor1; o[nt][3] *= cor1;
        }
        float s0 = 0.f, s1 = 0.f;
#pragma unroll
        for (int j = 0; j < 8; j++) {
            float p00 = __expf(c[j][0] - m0n);
            float p01 = __expf(c[j][1] - m0n);
            float p10 = __expf(c[j][2] - m1n);
            float p11 = __expf(c[j][3] - m1n);
            s0 += p00 + p01; s1 += p10 + p11;
            Ps[w][g][j * 8 + 2 * q4]     = cvt_tf32(p00);
            Ps[w][g][j * 8 + 2 * q4 + 1] = cvt_tf32(p01);
            Ps[w][g + 8][j * 8 + 2 * q4]     = cvt_tf32(p10);
            Ps[w][g + 8][j * 8 + 2 * q4 + 1] = cvt_tf32(p11);
        }
        s0 += __shfl_xor_sync(0xffffffffu, s0, 1);
        s0 += __shfl_xor_sync(0xffffffffu, s0, 2);
        s1 += __shfl_xor_sync(0xffffffffu, s1, 1);
        s1 += __shfl_xor_sync(0xffffffffu, s1, 2);
        l0 += s0; l1 += s1;
        m0 = m0n; m1 = m1n;
        __syncwarp();

        // ---- PV: o += P @ V
#pragma unroll
        for (int kt = 0; kt < 8; kt++) {
            unsigned a0 = Ps[w][g][kt * 8 + q4];
            unsigned a1 = Ps[w][g + 8][kt * 8 + q4];
            unsigned a2 = Ps[w][g][kt * 8 + q4 + 4];
            unsigned a3 = Ps[w][g + 8][kt * 8 + q4 + 4];
#pragma unroll
            for (int nt = 0; nt < 4; nt++) {
                unsigned b0 = Vs[kt * 8 + q4][nt * 8 + g];
                unsigned b1 = Vs[kt * 8 + q4 + 4][nt * 8 + g];
                mma_tf32(o[nt], a0, a1, a2, a3, b0, b1);
            }
        }
        __syncwarp();
    }

    // ---- emit split partials
    const int qh0 = (q0 + r0) * HH + h;
    const int qh1 = (q0 + r0 + 8) * HH + h;
    if (q4 == 0) {
        g_ml[sp * (NN * HH) + qh0] = make_float2(m0, l0);
        g_ml[sp * (NN * HH) + qh1] = make_float2(m1, l1);
    }
    float* op0 = g_opart + (size_t)(sp * (NN * HH) + qh0) * HDIM;
    float* op1 = g_opart + (size_t)(sp * (NN * HH) + qh1) * HDIM;
#pragma unroll
    for (int nt = 0; nt < 4; nt++) {
        int dc = nt * 8 + 2 * q4;
        op0[dc]     = o[nt][0];
        op0[dc + 1] = o[nt][1];
        op1[dc]     = o[nt][2];
        op1[dc + 1] = o[nt][3];
    }
}

// Merge ASPLIT partials: standard log-sum-exp combine.
__global__ void __launch_bounds__(256) attn_reduce_kernel()
{
    const int idx = blockIdx.x * blockDim.x + threadIdx.x;  // N*H*32
    const int dd = idx & (HDIM - 1);
    const int qh = idx >> 5;

    float2 ml[ASPLIT];
    float M = -1e30f;
#pragma unroll
    for (int s = 0; s < ASPLIT; s++) {
        ml[s] = g_ml[s * (NN * HH) + qh];
        M = fmaxf(M, ml[s].x);
    }
    float L = 0.f, o = 0.f;
#pragma unroll
    for (int s = 0; s < ASPLIT; s++) {
        float w = __expf(ml[s].x - M);
        L = fmaf(ml[s].y, w, L);
        o = fmaf(g_opart[(size_t)(s * (NN * HH) + qh) * HDIM + dd], w, o);
    }
    g_ao[idx] = o / L;
}

// ---------------- host launch ----------------
extern "C" void kernel_launch(void* const* d_in, const int* in_sizes, int n_in,
                              void* d_out, int out_size) {
    const float* x    = (const float*)d_in[0];
    const void*  ei   = (const void*)d_in[1];
    const float* ea   = (const float*)d_in[2];
    const float* eps  = (const float*)d_in[3];
    const float* Wl   = (const float*)d_in[4];
    const float* bl   = (const float*)d_in[5];
    const float* W1   = (const float*)d_in[6];
    const float* b1   = (const float*)d_in[7];
    const float* W2   = (const float*)d_in[8];
    const float* b2   = (const float*)d_in[9];
    const float* lnlg = (const float*)d_in[10];
    const float* lnlb = (const float*)d_in[11];
    const float* inw  = (const float*)d_in[12];
    const float* inb  = (const float*)d_in[13];
    const float* outw = (const float*)d_in[14];
    const float* outb = (const float*)d_in[15];
    const float* lnag = (const float*)d_in[16];
    const float* lnab = (const float*)d_in[17];
    const float* Wf1  = (const float*)d_in[18];
    const float* bf1  = (const float*)d_in[19];
    const float* Wf2  = (const float*)d_in[20];
    const float* bf2  = (const float*)d_in[21];
    const float* lnfg = (const float*)d_in[22];
    const float* lnfb = (const float*)d_in[23];
    float* out = (float*)d_out;

    const int E = in_sizes[1] / 2;

    // Buffer ids: 1=h 2=t1 3=h2 4=x1 5=qkv 6=ao 7=o2 8=x2 9=f1 10=f2 11=T

    // ---- GINEConv (CSR gather, tensor-core edge GEMM, zero float atomics)
    detect_idx_kernel<<<1, 1>>>((const unsigned int*)ei);
    zero_off_kernel<<<(NN + 256) / 256, 256>>>();
    hist_kernel<<<(E + 255) / 256, 256>>>(ei, E);
    scan_kernel<<<1, 1024>>>();
    fill_kernel<<<(E + 255) / 256, 256>>>(ei, E);
    // T = ea @ Wl + bl  (E x 256 from K=64)
    gemm_tf32_kernel<0, false, -1, 11><<<dim3(E / 128, DD / 64), 256>>>(ea, Wl, bl, E, DD, EDD);
    gine_aggregate_kernel<<<NN, 256>>>(x, eps);

    // ---- local MLP: h2 = elu(h@W1+b1)@W2+b2 ; x1 = x + elu(ln_l(h2))
    gemm_tf32_kernel<1, false, 1, 2><<<dim3(NN / 128, DD / 64), 256>>>(nullptr, W1, b1, NN, DD, DD);
    gemm_tf32_kernel<0, false, 2, 3><<<dim3(NN / 128, DD / 64), 256>>>(nullptr, W2, b2, NN, DD, DD);
    ln_res_kernel<1, -1, 3, 4><<<NN, 256>>>(x, nullptr, lnlg, lnlb);

    // ---- attention
    gemm_tf32_kernel<0, true, 4, 5><<<dim3(NN / 128, 3 * DD / 64), 256>>>(nullptr, inw, inb, NN, 3 * DD, DD);
    attn_mma_kernel<<<dim3(NN / QT, HH, ASPLIT), 128>>>(NN);
    attn_reduce_kernel<<<(NN * HH * HDIM) / 256, 256>>>();
    gemm_tf32_kernel<0, true, 6, 7><<<dim3(NN / 128, DD / 64), 256>>>(nullptr, outw, outb, NN, DD, DD);
    ln_res_kernel<0, 4, 7, 8><<<NN, 256>>>(nullptr, nullptr, lnag, lnab);

    // ---- FFN
    gemm_tf32_kernel<2, false, 8, 9><<<dim3(NN / 128, 2 * DD / 64), 256>>>(nullptr, Wf1, bf1, NN, 2 * DD, DD);
    gemm_tf32_kernel<0, false, 9, 10><<<dim3(NN / 128, DD / 64), 256>>>(nullptr, Wf2, bf2, NN, DD, 2 * DD);
    ln_res_kernel<0, 8, 10, -1><<<NN, 256>>>(nullptr, out, lnfg, lnfb);
}